// round 1
// baseline (speedup 1.0000x reference)
#include <cuda_runtime.h>

#define BATCH 32
#define CH    256
#define NPIX  1024
#define GROUPS 8
#define CPG   32
#define EPSV  1e-5f

#define BM 128
#define BN 128
#define BK 16
#define PAD 4

// ---- scratch (static device globals: allocation-free) ----
__device__ float g_q   [(size_t)BATCH * CH   * NPIX];   // [b][c][n]
__device__ float g_k   [(size_t)BATCH * CH   * NPIX];   // [b][c][n]
__device__ float g_vT  [(size_t)BATCH * NPIX * CH  ];   // [b][n][c]
__device__ float g_S   [(size_t)BATCH * NPIX * NPIX];   // [b][n][m]  128MB
__device__ float g_out [(size_t)BATCH * NPIX * CH  ];   // [b][n][c]
__device__ float g_scale[BATCH * CH];
__device__ float g_shift[BATCH * CH];

// ---------------- GroupNorm stats -> per-(b,c) scale/shift ----------------
__global__ __launch_bounds__(256) void gn_stats(const float* __restrict__ x,
                                                const float* __restrict__ nw,
                                                const float* __restrict__ nb) {
    int bg = blockIdx.x;               // B*GROUPS = 256
    int b = bg / GROUPS, g = bg % GROUPS;
    const float* p = x + ((size_t)b * CH + (size_t)g * CPG) * NPIX;
    float s = 0.f, sq = 0.f;
    for (int i = threadIdx.x; i < CPG * NPIX; i += 256) {
        float v = p[i];
        s += v; sq += v * v;
    }
    __shared__ float ss[256], ssq[256];
    ss[threadIdx.x] = s; ssq[threadIdx.x] = sq;
    __syncthreads();
    for (int ofs = 128; ofs > 0; ofs >>= 1) {
        if (threadIdx.x < ofs) {
            ss[threadIdx.x]  += ss[threadIdx.x + ofs];
            ssq[threadIdx.x] += ssq[threadIdx.x + ofs];
        }
        __syncthreads();
    }
    if (threadIdx.x < CPG) {
        const float inv_n = 1.f / (float)(CPG * NPIX);
        float mean = ss[0] * inv_n;
        float var  = ssq[0] * inv_n - mean * mean;
        float rstd = rsqrtf(var + EPSV);
        int c = g * CPG + threadIdx.x;
        float sc = rstd * nw[c];
        g_scale[b * CH + c] = sc;
        g_shift[b * CH + c] = nb[c] - mean * sc;
    }
}

// ---------------- QKV GEMM: qkv[o,n] = sum_c W[o,c] * (scale[c]*x[c,n]+shift[c]) ----
// Epilogue routes rows to q / k / vT(transposed).
__global__ __launch_bounds__(256) void qkv_gemm(const float* __restrict__ x,
                                                const float* __restrict__ W) {
    __shared__ float As[BK][BM + PAD];
    __shared__ float Bs[BK][BN + PAD];
    const int b  = blockIdx.z;
    const int m0 = blockIdx.y * BM;     // o in [0,768)
    const int n0 = blockIdx.x * BN;     // n in [0,1024)
    const float* xb  = x + (size_t)b * CH * NPIX;
    const float* scl = g_scale + b * CH;
    const float* sft = g_shift + b * CH;
    const int tid = threadIdx.x;
    const int tx = tid & 15, ty = tid >> 4;

    float acc[8][8];
    #pragma unroll
    for (int i = 0; i < 8; i++)
        #pragma unroll
        for (int j = 0; j < 8; j++) acc[i][j] = 0.f;

    for (int k0 = 0; k0 < CH; k0 += BK) {
        #pragma unroll
        for (int r = 0; r < 8; r++) {
            int id = tid + r * 256;
            int k = id & 15, m = id >> 4;
            As[k][m] = W[(size_t)(m0 + m) * CH + k0 + k];
        }
        #pragma unroll
        for (int r = 0; r < 8; r++) {
            int id = tid + r * 256;
            int n = id & 127, k = id >> 7;
            int c = k0 + k;
            Bs[k][n] = xb[(size_t)c * NPIX + n0 + n] * scl[c] + sft[c];
        }
        __syncthreads();
        #pragma unroll
        for (int kk = 0; kk < BK; kk++) {
            float a[8], bv[8];
            #pragma unroll
            for (int i = 0; i < 8; i++) a[i] = As[kk][ty * 8 + i];
            #pragma unroll
            for (int j = 0; j < 8; j++) bv[j] = Bs[kk][tx * 8 + j];
            #pragma unroll
            for (int i = 0; i < 8; i++)
                #pragma unroll
                for (int j = 0; j < 8; j++) acc[i][j] += a[i] * bv[j];
        }
        __syncthreads();
    }

    if (m0 < 256) {
        float* dst = g_q + (size_t)b * CH * NPIX;
        #pragma unroll
        for (int i = 0; i < 8; i++)
            #pragma unroll
            for (int j = 0; j < 8; j++)
                dst[(size_t)(m0 + ty * 8 + i) * NPIX + n0 + tx * 8 + j] = acc[i][j];
    } else if (m0 < 512) {
        float* dst = g_k + (size_t)b * CH * NPIX;
        #pragma unroll
        for (int i = 0; i < 8; i++)
            #pragma unroll
            for (int j = 0; j < 8; j++)
                dst[(size_t)(m0 - 256 + ty * 8 + i) * NPIX + n0 + tx * 8 + j] = acc[i][j];
    } else {
        float* dst = g_vT + (size_t)b * NPIX * CH;
        #pragma unroll
        for (int i = 0; i < 8; i++)
            #pragma unroll
            for (int j = 0; j < 8; j++)
                dst[(size_t)(n0 + tx * 8 + j) * CH + (m0 - 512 + ty * 8 + i)] = acc[i][j];
    }
}

// ---------------- S = (QᵀK) / 16 :  S[n,m] = sum_c q[c,n]*k[c,m] ----------------
__global__ __launch_bounds__(256) void s_gemm() {
    __shared__ float As[BK][BM + PAD];
    __shared__ float Bs[BK][BN + PAD];
    const int b  = blockIdx.z;
    const int m0 = blockIdx.y * BM;   // n index (query)
    const int n0 = blockIdx.x * BN;   // m index (key)
    const float* q  = g_q + (size_t)b * CH * NPIX;
    const float* km = g_k + (size_t)b * CH * NPIX;
    const int tid = threadIdx.x;
    const int tx = tid & 15, ty = tid >> 4;

    float acc[8][8];
    #pragma unroll
    for (int i = 0; i < 8; i++)
        #pragma unroll
        for (int j = 0; j < 8; j++) acc[i][j] = 0.f;

    for (int k0 = 0; k0 < CH; k0 += BK) {
        #pragma unroll
        for (int r = 0; r < 8; r++) {
            int id = tid + r * 256;
            int m = id & 127, k = id >> 7;
            As[k][m] = q[(size_t)(k0 + k) * NPIX + m0 + m];
        }
        #pragma unroll
        for (int r = 0; r < 8; r++) {
            int id = tid + r * 256;
            int n = id & 127, k = id >> 7;
            Bs[k][n] = km[(size_t)(k0 + k) * NPIX + n0 + n];
        }
        __syncthreads();
        #pragma unroll
        for (int kk = 0; kk < BK; kk++) {
            float a[8], bv[8];
            #pragma unroll
            for (int i = 0; i < 8; i++) a[i] = As[kk][ty * 8 + i];
            #pragma unroll
            for (int j = 0; j < 8; j++) bv[j] = Bs[kk][tx * 8 + j];
            #pragma unroll
            for (int i = 0; i < 8; i++)
                #pragma unroll
                for (int j = 0; j < 8; j++) acc[i][j] += a[i] * bv[j];
        }
        __syncthreads();
    }

    float* dst = g_S + (size_t)b * NPIX * NPIX;
    #pragma unroll
    for (int i = 0; i < 8; i++)
        #pragma unroll
        for (int j = 0; j < 8; j++)
            dst[(size_t)(m0 + ty * 8 + i) * NPIX + n0 + tx * 8 + j] = acc[i][j] * 0.0625f;
}

// ---------------- row softmax over g_S (in place) ----------------
__global__ __launch_bounds__(256) void softmax_rows() {
    float* p = g_S + (size_t)blockIdx.x * NPIX;
    const int t = threadIdx.x;
    float v[4];
    float mx = -3.4e38f;
    #pragma unroll
    for (int i = 0; i < 4; i++) { v[i] = p[t + i * 256]; mx = fmaxf(mx, v[i]); }
    __shared__ float red[256];
    red[t] = mx;
    __syncthreads();
    for (int ofs = 128; ofs > 0; ofs >>= 1) {
        if (t < ofs) red[t] = fmaxf(red[t], red[t + ofs]);
        __syncthreads();
    }
    mx = red[0];
    __syncthreads();
    float s = 0.f;
    #pragma unroll
    for (int i = 0; i < 4; i++) { v[i] = __expf(v[i] - mx); s += v[i]; }
    red[t] = s;
    __syncthreads();
    for (int ofs = 128; ofs > 0; ofs >>= 1) {
        if (t < ofs) red[t] += red[t + ofs];
        __syncthreads();
    }
    float inv = 1.f / red[0];
    #pragma unroll
    for (int i = 0; i < 4; i++) p[t + i * 256] = v[i] * inv;
}

// ---------------- O = P @ vT :  out[n,c] = sum_m P[n,m] * vT[m,c] ----------------
__global__ __launch_bounds__(256) void o_gemm() {
    __shared__ float As[BK][BM + PAD];
    __shared__ float Bs[BK][BN + PAD];
    const int b  = blockIdx.z;
    const int m0 = blockIdx.y * BM;   // n
    const int n0 = blockIdx.x * BN;   // c in [0,256)
    const float* P  = g_S  + (size_t)b * NPIX * NPIX;
    const float* vT = g_vT + (size_t)b * NPIX * CH;
    const int tid = threadIdx.x;
    const int tx = tid & 15, ty = tid >> 4;

    float acc[8][8];
    #pragma unroll
    for (int i = 0; i < 8; i++)
        #pragma unroll
        for (int j = 0; j < 8; j++) acc[i][j] = 0.f;

    for (int k0 = 0; k0 < NPIX; k0 += BK) {
        #pragma unroll
        for (int r = 0; r < 8; r++) {
            int id = tid + r * 256;
            int k = id & 15, m = id >> 4;
            As[k][m] = P[(size_t)(m0 + m) * NPIX + k0 + k];
        }
        #pragma unroll
        for (int r = 0; r < 8; r++) {
            int id = tid + r * 256;
            int n = id & 127, k = id >> 7;
            Bs[k][n] = vT[(size_t)(k0 + k) * CH + n0 + n];
        }
        __syncthreads();
        #pragma unroll
        for (int kk = 0; kk < BK; kk++) {
            float a[8], bv[8];
            #pragma unroll
            for (int i = 0; i < 8; i++) a[i] = As[kk][ty * 8 + i];
            #pragma unroll
            for (int j = 0; j < 8; j++) bv[j] = Bs[kk][tx * 8 + j];
            #pragma unroll
            for (int i = 0; i < 8; i++)
                #pragma unroll
                for (int j = 0; j < 8; j++) acc[i][j] += a[i] * bv[j];
        }
        __syncthreads();
    }

    float* dst = g_out + (size_t)b * NPIX * CH;
    #pragma unroll
    for (int i = 0; i < 8; i++)
        #pragma unroll
        for (int j = 0; j < 8; j++)
            dst[(size_t)(m0 + ty * 8 + i) * CH + n0 + tx * 8 + j] = acc[i][j];
}

// ---------------- proj + bias + residual: y[o,n] = x[o,n] + pb[o] + sum_c W[o,c]*out[n,c]
__global__ __launch_bounds__(256) void proj_gemm(const float* __restrict__ x,
                                                 const float* __restrict__ W,
                                                 const float* __restrict__ pb,
                                                 float* __restrict__ y) {
    __shared__ float As[BK][BM + PAD];
    __shared__ float Bs[BK][BN + PAD];
    const int b  = blockIdx.z;
    const int m0 = blockIdx.y * BM;   // o in [0,256)
    const int n0 = blockIdx.x * BN;   // n
    const float* ob = g_out + (size_t)b * NPIX * CH;
    const int tid = threadIdx.x;
    const int tx = tid & 15, ty = tid >> 4;

    float acc[8][8];
    #pragma unroll
    for (int i = 0; i < 8; i++)
        #pragma unroll
        for (int j = 0; j < 8; j++) acc[i][j] = 0.f;

    for (int k0 = 0; k0 < CH; k0 += BK) {
        #pragma unroll
        for (int r = 0; r < 8; r++) {
            int id = tid + r * 256;
            int k = id & 15, m = id >> 4;
            As[k][m] = W[(size_t)(m0 + m) * CH + k0 + k];
        }
        // B[k][n] = out[n0+n][k0+k]  (contiguous along k)
        #pragma unroll
        for (int r = 0; r < 8; r++) {
            int id = tid + r * 256;
            int k = id & 15, n = id >> 4;
            Bs[k][n] = ob[(size_t)(n0 + n) * CH + k0 + k];
        }
        __syncthreads();
        #pragma unroll
        for (int kk = 0; kk < BK; kk++) {
            float a[8], bv[8];
            #pragma unroll
            for (int i = 0; i < 8; i++) a[i] = As[kk][ty * 8 + i];
            #pragma unroll
            for (int j = 0; j < 8; j++) bv[j] = Bs[kk][tx * 8 + j];
            #pragma unroll
            for (int i = 0; i < 8; i++)
                #pragma unroll
                for (int j = 0; j < 8; j++) acc[i][j] += a[i] * bv[j];
        }
        __syncthreads();
    }

    const float* xb = x + (size_t)b * CH * NPIX;
    float* yb = y + (size_t)b * CH * NPIX;
    #pragma unroll
    for (int i = 0; i < 8; i++) {
        int o = m0 + ty * 8 + i;
        float bias = pb[o];
        #pragma unroll
        for (int j = 0; j < 8; j++) {
            size_t idx = (size_t)o * NPIX + n0 + tx * 8 + j;
            yb[idx] = xb[idx] + bias + acc[i][j];
        }
    }
}

extern "C" void kernel_launch(void* const* d_in, const int* in_sizes, int n_in,
                              void* d_out, int out_size) {
    const float* x      = (const float*)d_in[0];
    const float* norm_w = (const float*)d_in[1];
    const float* norm_b = (const float*)d_in[2];
    const float* qkv_w  = (const float*)d_in[3];
    const float* proj_w = (const float*)d_in[4];
    const float* proj_b = (const float*)d_in[5];
    float* y = (float*)d_out;

    gn_stats<<<BATCH * GROUPS, 256>>>(x, norm_w, norm_b);
    qkv_gemm<<<dim3(NPIX / BN, (3 * CH) / BM, BATCH), 256>>>(x, qkv_w);
    s_gemm<<<dim3(NPIX / BN, NPIX / BM, BATCH), 256>>>();
    softmax_rows<<<BATCH * NPIX, 256>>>();
    o_gemm<<<dim3(CH / BN, NPIX / BM, BATCH), 256>>>();
    proj_gemm<<<dim3(NPIX / BN, CH / BM, BATCH), 256>>>(x, proj_w, proj_b, y);
}

// round 2
// speedup vs baseline: 3.0344x; 3.0344x over previous
#include <cuda_runtime.h>
#include <stdint.h>

#define BATCH 32
#define CH    256
#define NPIX  1024
#define GROUPS 8
#define CPG   32
#define EPSV  1e-5f

#define BM 128
#define BN 128
#define BKT 16
#define LDAS 20
#define LDBS 136

// ---- scratch (static device globals: allocation-free) ----
__device__ float g_qT [(size_t)BATCH * NPIX * CH];   // [b][n][c]
__device__ float g_k  [(size_t)BATCH * CH * NPIX];   // [b][c][m]
__device__ float g_vT [(size_t)BATCH * NPIX * CH];   // [b][m][c]
__device__ float g_S  [(size_t)BATCH * NPIX * NPIX]; // [b][n][m]
__device__ float g_out[(size_t)BATCH * NPIX * CH];   // [b][n][c]
__device__ float g_scale[BATCH * CH];
__device__ float g_shift[BATCH * CH];

__device__ __forceinline__ uint32_t f2tf(float f) {
    uint32_t u;
    asm("cvt.rna.tf32.f32 %0, %1;" : "=r"(u) : "f"(f));
    return u;
}

__device__ __forceinline__ void mma_tf32(float c[4], const uint32_t a[4], const uint32_t b[2]) {
    asm volatile("mma.sync.aligned.m16n8k8.row.col.f32.tf32.tf32.f32 "
                 "{%0,%1,%2,%3}, {%4,%5,%6,%7}, {%8,%9}, {%0,%1,%2,%3};\n"
                 : "+f"(c[0]), "+f"(c[1]), "+f"(c[2]), "+f"(c[3])
                 : "r"(a[0]), "r"(a[1]), "r"(a[2]), "r"(a[3]),
                   "r"(b[0]), "r"(b[1]));
}

// As: [BM][LDAS] row-major (row = M, col = K).  Bs: [BKT][LDBS] (row = K, col = N).
__device__ __forceinline__ void compute_tile(const float* __restrict__ As,
                                             const float* __restrict__ Bs,
                                             float acc[4][4][4],
                                             int wm, int wn, int gr, int tg) {
    #pragma unroll
    for (int k0 = 0; k0 < BKT; k0 += 8) {
        uint32_t a[4][4], bf[4][2];
        #pragma unroll
        for (int i = 0; i < 4; i++) {
            const float* p = As + (wm * 64 + i * 16 + gr) * LDAS + k0 + tg;
            a[i][0] = __float_as_uint(p[0]);
            a[i][1] = __float_as_uint(p[8 * LDAS]);
            a[i][2] = __float_as_uint(p[4]);
            a[i][3] = __float_as_uint(p[8 * LDAS + 4]);
        }
        #pragma unroll
        for (int j = 0; j < 4; j++) {
            const float* p = Bs + (k0 + tg) * LDBS + wn * 32 + j * 8 + gr;
            bf[j][0] = __float_as_uint(p[0]);
            bf[j][1] = __float_as_uint(p[4 * LDBS]);
        }
        #pragma unroll
        for (int i = 0; i < 4; i++)
            #pragma unroll
            for (int j = 0; j < 4; j++)
                mma_tf32(acc[i][j], a[i], bf[j]);
    }
}

// ---------------- GroupNorm stats -> per-(b,c) scale/shift ----------------
__global__ __launch_bounds__(256) void gn_stats(const float* __restrict__ x,
                                                const float* __restrict__ nw,
                                                const float* __restrict__ nb) {
    int bg = blockIdx.x;
    int b = bg / GROUPS, g = bg % GROUPS;
    const float4* p4 = (const float4*)(x + ((size_t)b * CH + (size_t)g * CPG) * NPIX);
    float s = 0.f, sq = 0.f;
    for (int i = threadIdx.x; i < CPG * NPIX / 4; i += 256) {
        float4 v = p4[i];
        s += v.x + v.y + v.z + v.w;
        sq += v.x * v.x + v.y * v.y + v.z * v.z + v.w * v.w;
    }
    #pragma unroll
    for (int o = 16; o; o >>= 1) {
        s  += __shfl_xor_sync(~0u, s, o);
        sq += __shfl_xor_sync(~0u, sq, o);
    }
    __shared__ float ss[8], ssq[8];
    if ((threadIdx.x & 31) == 0) { ss[threadIdx.x >> 5] = s; ssq[threadIdx.x >> 5] = sq; }
    __syncthreads();
    if (threadIdx.x < CPG) {
        float st = 0.f, sqt = 0.f;
        #pragma unroll
        for (int i = 0; i < 8; i++) { st += ss[i]; sqt += ssq[i]; }
        const float inv_n = 1.f / (float)(CPG * NPIX);
        float mean = st * inv_n;
        float var  = sqt * inv_n - mean * mean;
        float rstd = rsqrtf(var + EPSV);
        int c = g * CPG + threadIdx.x;
        float sc = rstd * nw[c];
        g_scale[b * CH + c] = sc;
        g_shift[b * CH + c] = nb[c] - mean * sc;
    }
}

// ---------------- QKV GEMM (tf32 mma): qkv[o,n] = sum_c W[o,c]*(scale[c]*x[c,n]+shift[c])
__global__ __launch_bounds__(256) void qkv_gemm(const float* __restrict__ x,
                                                const float* __restrict__ W) {
    __shared__ float As[2][BM * LDAS];
    __shared__ float Bs[2][BKT * LDBS];
    const int b = blockIdx.z, m0 = blockIdx.y * BM, n0 = blockIdx.x * BN;
    const int tid = threadIdx.x;
    const int wid = tid >> 5, lane = tid & 31, gr = lane >> 2, tg = lane & 3;
    const int wm = wid >> 2, wn = wid & 3;
    const float* Abase = W + (size_t)m0 * CH;
    const float* xb = x + (size_t)b * CH * NPIX + n0;
    const float* scl = g_scale + b * CH;
    const float* sft = g_shift + b * CH;

    float acc[4][4][4] = {};
    float4 ra[2], rb[2];
    float rs[2], rh[2];

    auto ldg = [&](int k0) {
        #pragma unroll
        for (int r = 0; r < 2; r++) {
            int idx = tid + r * 256;
            int row = idx >> 2, c4 = (idx & 3) << 2;
            ra[r] = *(const float4*)(Abase + (size_t)row * CH + k0 + c4);
            int k = idx >> 5, n4 = (idx & 31) << 2;
            rb[r] = *(const float4*)(xb + (size_t)(k0 + k) * NPIX + n4);
            rs[r] = scl[k0 + k];
            rh[r] = sft[k0 + k];
        }
    };
    auto sts = [&](int buf) {
        #pragma unroll
        for (int r = 0; r < 2; r++) {
            int idx = tid + r * 256;
            int row = idx >> 2, c4 = (idx & 3) << 2;
            uint4 ua = { f2tf(ra[r].x), f2tf(ra[r].y), f2tf(ra[r].z), f2tf(ra[r].w) };
            *(uint4*)&As[buf][row * LDAS + c4] = ua;
            int k = idx >> 5, n4 = (idx & 31) << 2;
            uint4 ub = { f2tf(fmaf(rb[r].x, rs[r], rh[r])), f2tf(fmaf(rb[r].y, rs[r], rh[r])),
                         f2tf(fmaf(rb[r].z, rs[r], rh[r])), f2tf(fmaf(rb[r].w, rs[r], rh[r])) };
            *(uint4*)&Bs[buf][k * LDBS + n4] = ub;
        }
    };

    const int NT = CH / BKT;
    ldg(0); sts(0); __syncthreads();
    for (int t = 0; t < NT; t++) {
        int cur = t & 1;
        if (t + 1 < NT) ldg((t + 1) * BKT);
        compute_tile(As[cur], Bs[cur], acc, wm, wn, gr, tg);
        if (t + 1 < NT) sts(cur ^ 1);
        __syncthreads();
    }

    if (m0 < CH) {                       // q -> transposed [n][c]
        float* dst = g_qT + (size_t)b * NPIX * CH;
        #pragma unroll
        for (int i = 0; i < 4; i++) {
            int row = m0 + wm * 64 + i * 16 + gr;
            #pragma unroll
            for (int j = 0; j < 4; j++) {
                int col = n0 + wn * 32 + j * 8 + tg * 2;
                dst[(size_t)col * CH + row]           = acc[i][j][0];
                dst[(size_t)(col + 1) * CH + row]     = acc[i][j][1];
                dst[(size_t)col * CH + row + 8]       = acc[i][j][2];
                dst[(size_t)(col + 1) * CH + row + 8] = acc[i][j][3];
            }
        }
    } else if (m0 < 2 * CH) {            // k -> [c][m]
        float* dst = g_k + (size_t)b * CH * NPIX;
        #pragma unroll
        for (int i = 0; i < 4; i++) {
            int row = m0 - CH + wm * 64 + i * 16 + gr;
            #pragma unroll
            for (int j = 0; j < 4; j++) {
                int col = n0 + wn * 32 + j * 8 + tg * 2;
                float* p = dst + (size_t)row * NPIX + col;
                p[0] = acc[i][j][0]; p[1] = acc[i][j][1];
                p[8 * NPIX] = acc[i][j][2]; p[8 * NPIX + 1] = acc[i][j][3];
            }
        }
    } else {                             // v -> transposed [m][c]
        float* dst = g_vT + (size_t)b * NPIX * CH;
        #pragma unroll
        for (int i = 0; i < 4; i++) {
            int row = m0 - 2 * CH + wm * 64 + i * 16 + gr;
            #pragma unroll
            for (int j = 0; j < 4; j++) {
                int col = n0 + wn * 32 + j * 8 + tg * 2;
                dst[(size_t)col * CH + row]           = acc[i][j][0];
                dst[(size_t)(col + 1) * CH + row]     = acc[i][j][1];
                dst[(size_t)col * CH + row + 8]       = acc[i][j][2];
                dst[(size_t)(col + 1) * CH + row + 8] = acc[i][j][3];
            }
        }
    }
}

// ---------------- S = (QᵀK)/16 :  S[n,m] = sum_c qT[n,c] * k[c,m] ----------------
__global__ __launch_bounds__(256) void s_gemm() {
    __shared__ float As[2][BM * LDAS];
    __shared__ float Bs[2][BKT * LDBS];
    const int b = blockIdx.z, m0 = blockIdx.y * BM, n0 = blockIdx.x * BN;
    const int tid = threadIdx.x;
    const int wid = tid >> 5, lane = tid & 31, gr = lane >> 2, tg = lane & 3;
    const int wm = wid >> 2, wn = wid & 3;
    const float* Abase = g_qT + (size_t)b * NPIX * CH + (size_t)m0 * CH;
    const float* Bbase = g_k  + (size_t)b * CH * NPIX + n0;

    float acc[4][4][4] = {};
    float4 ra[2], rb[2];

    auto ldg = [&](int k0) {
        #pragma unroll
        for (int r = 0; r < 2; r++) {
            int idx = tid + r * 256;
            int row = idx >> 2, c4 = (idx & 3) << 2;
            ra[r] = *(const float4*)(Abase + (size_t)row * CH + k0 + c4);
            int k = idx >> 5, n4 = (idx & 31) << 2;
            rb[r] = *(const float4*)(Bbase + (size_t)(k0 + k) * NPIX + n4);
        }
    };
    auto sts = [&](int buf) {
        #pragma unroll
        for (int r = 0; r < 2; r++) {
            int idx = tid + r * 256;
            int row = idx >> 2, c4 = (idx & 3) << 2;
            uint4 ua = { f2tf(ra[r].x), f2tf(ra[r].y), f2tf(ra[r].z), f2tf(ra[r].w) };
            *(uint4*)&As[buf][row * LDAS + c4] = ua;
            int k = idx >> 5, n4 = (idx & 31) << 2;
            uint4 ub = { f2tf(rb[r].x), f2tf(rb[r].y), f2tf(rb[r].z), f2tf(rb[r].w) };
            *(uint4*)&Bs[buf][k * LDBS + n4] = ub;
        }
    };

    const int NT = CH / BKT;
    ldg(0); sts(0); __syncthreads();
    for (int t = 0; t < NT; t++) {
        int cur = t & 1;
        if (t + 1 < NT) ldg((t + 1) * BKT);
        compute_tile(As[cur], Bs[cur], acc, wm, wn, gr, tg);
        if (t + 1 < NT) sts(cur ^ 1);
        __syncthreads();
    }

    float* dst = g_S + (size_t)b * NPIX * NPIX;
    #pragma unroll
    for (int i = 0; i < 4; i++) {
        int row = m0 + wm * 64 + i * 16 + gr;
        #pragma unroll
        for (int j = 0; j < 4; j++) {
            int col = n0 + wn * 32 + j * 8 + tg * 2;
            float* p = dst + (size_t)row * NPIX + col;
            p[0] = acc[i][j][0] * 0.0625f; p[1] = acc[i][j][1] * 0.0625f;
            p[8 * NPIX] = acc[i][j][2] * 0.0625f; p[8 * NPIX + 1] = acc[i][j][3] * 0.0625f;
        }
    }
}

// ---------------- row softmax over g_S (in place, float4 + shuffles) ----------------
__global__ __launch_bounds__(256) void softmax_rows() {
    float4* p = (float4*)(g_S + (size_t)blockIdx.x * NPIX);
    const int t = threadIdx.x;
    float4 v = p[t];
    float mx = fmaxf(fmaxf(v.x, v.y), fmaxf(v.z, v.w));
    #pragma unroll
    for (int o = 16; o; o >>= 1) mx = fmaxf(mx, __shfl_xor_sync(~0u, mx, o));
    __shared__ float red[8];
    if ((t & 31) == 0) red[t >> 5] = mx;
    __syncthreads();
    mx = red[0];
    #pragma unroll
    for (int i = 1; i < 8; i++) mx = fmaxf(mx, red[i]);
    __syncthreads();
    v.x = __expf(v.x - mx); v.y = __expf(v.y - mx);
    v.z = __expf(v.z - mx); v.w = __expf(v.w - mx);
    float s = v.x + v.y + v.z + v.w;
    #pragma unroll
    for (int o = 16; o; o >>= 1) s += __shfl_xor_sync(~0u, s, o);
    if ((t & 31) == 0) red[t >> 5] = s;
    __syncthreads();
    s = 0.f;
    #pragma unroll
    for (int i = 0; i < 8; i++) s += red[i];
    float inv = 1.f / s;
    v.x *= inv; v.y *= inv; v.z *= inv; v.w *= inv;
    p[t] = v;
}

// ---------------- O = P @ vT :  out[n,c] = sum_m P[n,m] * vT[m,c] ----------------
__global__ __launch_bounds__(256) void o_gemm() {
    __shared__ float As[2][BM * LDAS];
    __shared__ float Bs[2][BKT * LDBS];
    const int b = blockIdx.z, m0 = blockIdx.y * BM, n0 = blockIdx.x * BN;
    const int tid = threadIdx.x;
    const int wid = tid >> 5, lane = tid & 31, gr = lane >> 2, tg = lane & 3;
    const int wm = wid >> 2, wn = wid & 3;
    const float* Abase = g_S  + (size_t)b * NPIX * NPIX + (size_t)m0 * NPIX;
    const float* Bbase = g_vT + (size_t)b * NPIX * CH + n0;

    float acc[4][4][4] = {};
    float4 ra[2], rb[2];

    auto ldg = [&](int k0) {
        #pragma unroll
        for (int r = 0; r < 2; r++) {
            int idx = tid + r * 256;
            int row = idx >> 2, c4 = (idx & 3) << 2;
            ra[r] = *(const float4*)(Abase + (size_t)row * NPIX + k0 + c4);
            int k = idx >> 5, n4 = (idx & 31) << 2;
            rb[r] = *(const float4*)(Bbase + (size_t)(k0 + k) * CH + n4);
        }
    };
    auto sts = [&](int buf) {
        #pragma unroll
        for (int r = 0; r < 2; r++) {
            int idx = tid + r * 256;
            int row = idx >> 2, c4 = (idx & 3) << 2;
            uint4 ua = { f2tf(ra[r].x), f2tf(ra[r].y), f2tf(ra[r].z), f2tf(ra[r].w) };
            *(uint4*)&As[buf][row * LDAS + c4] = ua;
            int k = idx >> 5, n4 = (idx & 31) << 2;
            uint4 ub = { f2tf(rb[r].x), f2tf(rb[r].y), f2tf(rb[r].z), f2tf(rb[r].w) };
            *(uint4*)&Bs[buf][k * LDBS + n4] = ub;
        }
    };

    const int NT = NPIX / BKT;   // 64
    ldg(0); sts(0); __syncthreads();
    for (int t = 0; t < NT; t++) {
        int cur = t & 1;
        if (t + 1 < NT) ldg((t + 1) * BKT);
        compute_tile(As[cur], Bs[cur], acc, wm, wn, gr, tg);
        if (t + 1 < NT) sts(cur ^ 1);
        __syncthreads();
    }

    float* dst = g_out + (size_t)b * NPIX * CH;
    #pragma unroll
    for (int i = 0; i < 4; i++) {
        int row = m0 + wm * 64 + i * 16 + gr;
        #pragma unroll
        for (int j = 0; j < 4; j++) {
            int col = n0 + wn * 32 + j * 8 + tg * 2;
            float* p = dst + (size_t)row * CH + col;
            p[0] = acc[i][j][0]; p[1] = acc[i][j][1];
            p[8 * CH] = acc[i][j][2]; p[8 * CH + 1] = acc[i][j][3];
        }
    }
}

// ---------------- proj + bias + residual ----------------
__global__ __launch_bounds__(256) void proj_gemm(const float* __restrict__ x,
                                                 const float* __restrict__ W,
                                                 const float* __restrict__ pb,
                                                 float* __restrict__ y) {
    __shared__ float As[2][BM * LDAS];
    __shared__ float Bs[2][BKT * LDBS];
    const int b = blockIdx.z, m0 = blockIdx.y * BM, n0 = blockIdx.x * BN;
    const int tid = threadIdx.x;
    const int wid = tid >> 5, lane = tid & 31, gr = lane >> 2, tg = lane & 3;
    const int wm = wid >> 2, wn = wid & 3;
    const float* Abase = W + (size_t)m0 * CH;
    const float* ob = g_out + (size_t)b * NPIX * CH + (size_t)n0 * CH;

    float acc[4][4][4] = {};
    float4 ra[2], rb[2];

    auto ldg = [&](int k0) {
        #pragma unroll
        for (int r = 0; r < 2; r++) {
            int idx = tid + r * 256;
            int row = idx >> 2, c4 = (idx & 3) << 2;
            ra[r] = *(const float4*)(Abase + (size_t)row * CH + k0 + c4);
            int n = idx & 127, cg = ((idx >> 7) & 3) << 2;   // transposed B read
            rb[r] = *(const float4*)(ob + (size_t)n * CH + k0 + cg);
        }
    };
    auto sts = [&](int buf) {
        #pragma unroll
        for (int r = 0; r < 2; r++) {
            int idx = tid + r * 256;
            int row = idx >> 2, c4 = (idx & 3) << 2;
            uint4 ua = { f2tf(ra[r].x), f2tf(ra[r].y), f2tf(ra[r].z), f2tf(ra[r].w) };
            *(uint4*)&As[buf][row * LDAS + c4] = ua;
            int n = idx & 127, cg = ((idx >> 7) & 3) << 2;
            Bs[buf][(cg + 0) * LDBS + n] = __uint_as_float(f2tf(rb[r].x));
            Bs[buf][(cg + 1) * LDBS + n] = __uint_as_float(f2tf(rb[r].y));
            Bs[buf][(cg + 2) * LDBS + n] = __uint_as_float(f2tf(rb[r].z));
            Bs[buf][(cg + 3) * LDBS + n] = __uint_as_float(f2tf(rb[r].w));
        }
    };

    const int NT = CH / BKT;
    ldg(0); sts(0); __syncthreads();
    for (int t = 0; t < NT; t++) {
        int cur = t & 1;
        if (t + 1 < NT) ldg((t + 1) * BKT);
        compute_tile(As[cur], Bs[cur], acc, wm, wn, gr, tg);
        if (t + 1 < NT) sts(cur ^ 1);
        __syncthreads();
    }

    const float* xb = x + (size_t)b * CH * NPIX;
    float* yb = y + (size_t)b * CH * NPIX;
    #pragma unroll
    for (int i = 0; i < 4; i++) {
        int row = m0 + wm * 64 + i * 16 + gr;
        float b0 = pb[row], b1 = pb[row + 8];
        #pragma unroll
        for (int j = 0; j < 4; j++) {
            int col = n0 + wn * 32 + j * 8 + tg * 2;
            size_t i0 = (size_t)row * NPIX + col;
            size_t i1 = (size_t)(row + 8) * NPIX + col;
            yb[i0]     = xb[i0]     + b0 + acc[i][j][0];
            yb[i0 + 1] = xb[i0 + 1] + b0 + acc[i][j][1];
            yb[i1]     = xb[i1]     + b1 + acc[i][j][2];
            yb[i1 + 1] = xb[i1 + 1] + b1 + acc[i][j][3];
        }
    }
}

extern "C" void kernel_launch(void* const* d_in, const int* in_sizes, int n_in,
                              void* d_out, int out_size) {
    const float* x      = (const float*)d_in[0];
    const float* norm_w = (const float*)d_in[1];
    const float* norm_b = (const float*)d_in[2];
    const float* qkv_w  = (const float*)d_in[3];
    const float* proj_w = (const float*)d_in[4];
    const float* proj_b = (const float*)d_in[5];
    float* y = (float*)d_out;

    gn_stats<<<BATCH * GROUPS, 256>>>(x, norm_w, norm_b);
    qkv_gemm<<<dim3(NPIX / BN, (3 * CH) / BM, BATCH), 256>>>(x, qkv_w);
    s_gemm<<<dim3(NPIX / BN, NPIX / BM, BATCH), 256>>>();
    softmax_rows<<<BATCH * NPIX, 256>>>();
    o_gemm<<<dim3(CH / BN, NPIX / BM, BATCH), 256>>>();
    proj_gemm<<<dim3(NPIX / BN, CH / BM, BATCH), 256>>>(x, proj_w, proj_b, y);
}

// round 4
// speedup vs baseline: 5.2834x; 1.7412x over previous
#include <cuda_runtime.h>
#include <cuda_bf16.h>
#include <stdint.h>

#define BATCH 32
#define CH    256
#define NPIX  1024
#define GROUPS 8
#define CPG   32
#define EPSV  1e-5f

#define BKC 32
#define LDA 40                     // bf16 elems per smem row (80B, conflict-free frags)
#define ATILE (128 * LDA)          // elems per operand tile
#define NSG 3
#define SMEM_REQ (NSG * 2 * ATILE * 2)   // 61440 bytes

typedef __nv_bfloat16 bf16;

// ---- scratch (static device globals: allocation-free) ----
__device__ bf16 g_hT [(size_t)BATCH * NPIX * CH];    // [b][n][c]
__device__ bf16 g_qT [(size_t)BATCH * NPIX * CH];    // [b][n][c] (W_q pre-scaled 1/16)
__device__ bf16 g_kT [(size_t)BATCH * NPIX * CH];    // [b][m][c]
__device__ bf16 g_v  [(size_t)BATCH * CH * NPIX];    // [b][c][m]
__device__ bf16 g_out[(size_t)BATCH * NPIX * CH];    // [b][n][c]
__device__ float g_S [(size_t)BATCH * NPIX * NPIX];  // [b][n][m] fp32 (exp sensitivity)
__device__ bf16 g_P  [(size_t)BATCH * NPIX * NPIX];  // [b][n][m] probs
__device__ bf16 g_wqk[(size_t)512 * CH];             // qkv_w rows 0..511 (q rows /16)
__device__ bf16 g_wv [(size_t)CH * CH];              // qkv_w rows 512..767
__device__ bf16 g_wp [(size_t)CH * CH];
__device__ float g_scale[BATCH * CH];
__device__ float g_shift[BATCH * CH];

// ================= helpers =================
__device__ __forceinline__ uint32_t smem_u32(const void* p) {
    uint32_t a;
    asm("{ .reg .u64 t; cvta.to.shared.u64 t, %1; cvt.u32.u64 %0, t; }" : "=r"(a) : "l"(p));
    return a;
}
__device__ __forceinline__ void cpa16(uint32_t d, const void* s) {
    asm volatile("cp.async.cg.shared.global [%0], [%1], 16;" :: "r"(d), "l"(s));
}
__device__ __forceinline__ uint32_t pk2(float lo, float hi) {   // -> {lo, hi} packed bf16x2
    uint32_t r;
    asm("cvt.rn.bf16x2.f32 %0, %1, %2;" : "=r"(r) : "f"(hi), "f"(lo));
    return r;
}
__device__ __forceinline__ void mma_bf16(float c[4], const uint32_t a[4], const uint32_t b[2]) {
    asm volatile("mma.sync.aligned.m16n8k16.row.col.f32.bf16.bf16.f32 "
                 "{%0,%1,%2,%3}, {%4,%5,%6,%7}, {%8,%9}, {%0,%1,%2,%3};\n"
                 : "+f"(c[0]), "+f"(c[1]), "+f"(c[2]), "+f"(c[3])
                 : "r"(a[0]), "r"(a[1]), "r"(a[2]), "r"(a[3]), "r"(b[0]), "r"(b[1]));
}

// ====== bf16 mma.sync GEMM core: D[128,128] = A[128,K] (row) * B[128,K]^T ======
// A, B bf16, k-contiguous rows. acc[i][j][4]: warp (wm=wid>>2: 2x64 M, wn=wid&3: 4x32 N).
template <int NT>
__device__ __forceinline__ void gemm_core(const bf16* __restrict__ A, int lda,
                                          const bf16* __restrict__ B, int ldb,
                                          float (&acc)[4][4][4]) {
    extern __shared__ bf16 sh[];
    const int tid = threadIdx.x;
    const int wid = tid >> 5, lane = tid & 31, gr = lane >> 2, tg = lane & 3;
    const int wm = wid >> 2, wn = wid & 3;

    auto load_stage = [&](int s, int t) {
        bf16* sa = sh + s * (2 * ATILE);
        bf16* sb = sa + ATILE;
        const bf16* ga = A + t * BKC;
        const bf16* gb = B + t * BKC;
        #pragma unroll
        for (int it = 0; it < 2; it++) {
            int c = tid + it * 256;
            int r = c >> 2, i = c & 3;          // 128 rows x 4 16B-chunks
            cpa16(smem_u32(sa + r * LDA + i * 8), ga + (size_t)r * lda + i * 8);
            cpa16(smem_u32(sb + r * LDA + i * 8), gb + (size_t)r * ldb + i * 8);
        }
        asm volatile("cp.async.commit_group;");
    };

    load_stage(0, 0);
    if (NT > 1) load_stage(1, 1);

    for (int t = 0; t < NT; t++) {
        if (t + 2 < NT) { load_stage((t + 2) % NSG, t + 2); asm volatile("cp.async.wait_group 2;"); }
        else if (t + 1 < NT) asm volatile("cp.async.wait_group 1;");
        else                 asm volatile("cp.async.wait_group 0;");
        __syncthreads();

        const bf16* sa = sh + (t % NSG) * (2 * ATILE);
        const bf16* sb = sa + ATILE;
        #pragma unroll
        for (int ks = 0; ks < BKC; ks += 16) {
            uint32_t a[4][4], b[4][2];
            #pragma unroll
            for (int i = 0; i < 4; i++) {
                const bf16* p = sa + (wm * 64 + i * 16 + gr) * LDA + ks + tg * 2;
                a[i][0] = *(const uint32_t*)p;
                a[i][1] = *(const uint32_t*)(p + 8 * LDA);
                a[i][2] = *(const uint32_t*)(p + 8);
                a[i][3] = *(const uint32_t*)(p + 8 * LDA + 8);
            }
            #pragma unroll
            for (int j = 0; j < 4; j++) {
                const bf16* p = sb + (wn * 32 + j * 8 + gr) * LDA + ks + tg * 2;
                b[j][0] = *(const uint32_t*)p;
                b[j][1] = *(const uint32_t*)(p + 8);
            }
            #pragma unroll
            for (int i = 0; i < 4; i++)
                #pragma unroll
                for (int j = 0; j < 4; j++)
                    mma_bf16(acc[i][j], a[i], b[j]);
        }
        __syncthreads();
    }
}

// ================= GroupNorm stats =================
__global__ __launch_bounds__(256) void gn_stats(const float* __restrict__ x,
                                                const float* __restrict__ nw,
                                                const float* __restrict__ nb) {
    int bg = blockIdx.x;
    int b = bg / GROUPS, g = bg % GROUPS;
    const float4* p4 = (const float4*)(x + ((size_t)b * CH + (size_t)g * CPG) * NPIX);
    float s = 0.f, sq = 0.f;
    for (int i = threadIdx.x; i < CPG * NPIX / 4; i += 256) {
        float4 v = p4[i];
        s += v.x + v.y + v.z + v.w;
        sq += v.x * v.x + v.y * v.y + v.z * v.z + v.w * v.w;
    }
    #pragma unroll
    for (int o = 16; o; o >>= 1) {
        s  += __shfl_xor_sync(~0u, s, o);
        sq += __shfl_xor_sync(~0u, sq, o);
    }
    __shared__ float ss[8], ssq[8];
    if ((threadIdx.x & 31) == 0) { ss[threadIdx.x >> 5] = s; ssq[threadIdx.x >> 5] = sq; }
    __syncthreads();
    if (threadIdx.x < CPG) {
        float st = 0.f, sqt = 0.f;
        #pragma unroll
        for (int i = 0; i < 8; i++) { st += ss[i]; sqt += ssq[i]; }
        const float inv_n = 1.f / (float)(CPG * NPIX);
        float mean = st * inv_n;
        float var  = sqt * inv_n - mean * mean;
        float rstd = rsqrtf(var + EPSV);
        int c = g * CPG + threadIdx.x;
        float sc = rstd * nw[c];
        g_scale[b * CH + c] = sc;
        g_shift[b * CH + c] = nb[c] - mean * sc;
    }
}

// ================= weights -> bf16 (q rows pre-scaled 1/16) =================
__global__ __launch_bounds__(256) void wcvt(const float* __restrict__ qkv_w,
                                            const float* __restrict__ proj_w) {
    int idx = blockIdx.x * 256 + threadIdx.x;     // grid covers (768+256)*256/4
    #pragma unroll
    for (int u = 0; u < 4; u++) {
        int e = idx * 4 + u;
        if (e < 768 * CH) {
            int row = e / CH;
            float v = qkv_w[e];
            if (row < CH) v *= 0.0625f;
            if (row < 512) g_wqk[e] = __float2bfloat16(v);
            else           g_wv[e - 512 * CH] = __float2bfloat16(v);
        } else {
            int e2 = e - 768 * CH;
            g_wp[e2] = __float2bfloat16(proj_w[e2]);
        }
    }
}

// ================= normalize + transpose: hT[b][n][c] bf16 =================
__global__ __launch_bounds__(256) void ht_kernel(const float* __restrict__ x) {
    __shared__ float tile[32][33];
    int b = blockIdx.z, c0 = blockIdx.y * 32, n0 = blockIdx.x * 32;
    int tx = threadIdx.x & 31, ty = threadIdx.x >> 5;
    const float* xb = x + ((size_t)b * CH + c0) * NPIX;
    #pragma unroll
    for (int k = 0; k < 4; k++) {
        int c = ty + k * 8;
        float sc = g_scale[b * CH + c0 + c], sh = g_shift[b * CH + c0 + c];
        tile[c][tx] = fmaf(xb[(size_t)c * NPIX + n0 + tx], sc, sh);
    }
    __syncthreads();
    bf16* dst = g_hT + (size_t)b * NPIX * CH;
    #pragma unroll
    for (int k = 0; k < 4; k++) {
        int n = ty + k * 8;
        dst[(size_t)(n0 + n) * CH + c0 + tx] = __float2bfloat16(tile[tx][n]);
    }
}

// ========== QK: D[n][o] = hT[n,:]·Wqk[o,:],  o<256 -> qT, else -> kT ==========
__global__ __launch_bounds__(256) void qk_gemm() {
    const int b = blockIdx.z, m0 = blockIdx.y * 128, n0 = blockIdx.x * 128;
    float acc[4][4][4] = {};
    gemm_core<CH / BKC>(g_hT + (size_t)b * NPIX * CH + (size_t)m0 * CH, CH,
                        g_wqk + (size_t)n0 * CH, CH, acc);
    const int wid = threadIdx.x >> 5, lane = threadIdx.x & 31, gr = lane >> 2, tg = lane & 3;
    const int wm = wid >> 2, wn = wid & 3;
    bf16* dst = (n0 < 256 ? g_qT : g_kT) + (size_t)b * NPIX * CH;
    const int c0 = n0 & 255;
    #pragma unroll
    for (int i = 0; i < 4; i++) {
        int row = m0 + wm * 64 + i * 16 + gr;
        #pragma unroll
        for (int j = 0; j < 4; j++) {
            int col = c0 + wn * 32 + j * 8 + tg * 2;
            *(uint32_t*)&dst[(size_t)row * CH + col]       = pk2(acc[i][j][0], acc[i][j][1]);
            *(uint32_t*)&dst[(size_t)(row + 8) * CH + col] = pk2(acc[i][j][2], acc[i][j][3]);
        }
    }
}

// ========== V: D[c][m] = Wv[c,:]·hT[m,:] -> g_v[c][m] ==========
__global__ __launch_bounds__(256) void v_gemm() {
    const int b = blockIdx.z, m0 = blockIdx.y * 128, n0 = blockIdx.x * 128;
    float acc[4][4][4] = {};
    gemm_core<CH / BKC>(g_wv + (size_t)m0 * CH, CH,
                        g_hT + (size_t)b * NPIX * CH + (size_t)n0 * CH, CH, acc);
    const int wid = threadIdx.x >> 5, lane = threadIdx.x & 31, gr = lane >> 2, tg = lane & 3;
    const int wm = wid >> 2, wn = wid & 3;
    bf16* dst = g_v + (size_t)b * CH * NPIX;
    #pragma unroll
    for (int i = 0; i < 4; i++) {
        int row = m0 + wm * 64 + i * 16 + gr;
        #pragma unroll
        for (int j = 0; j < 4; j++) {
            int col = n0 + wn * 32 + j * 8 + tg * 2;
            *(uint32_t*)&dst[(size_t)row * NPIX + col]       = pk2(acc[i][j][0], acc[i][j][1]);
            *(uint32_t*)&dst[(size_t)(row + 8) * NPIX + col] = pk2(acc[i][j][2], acc[i][j][3]);
        }
    }
}

// ========== S[n][m] = qT[n,:]·kT[m,:]  (fp32 out) ==========
__global__ __launch_bounds__(256) void s_gemm() {
    const int b = blockIdx.z, m0 = blockIdx.y * 128, n0 = blockIdx.x * 128;
    float acc[4][4][4] = {};
    gemm_core<CH / BKC>(g_qT + (size_t)b * NPIX * CH + (size_t)m0 * CH, CH,
                        g_kT + (size_t)b * NPIX * CH + (size_t)n0 * CH, CH, acc);
    const int wid = threadIdx.x >> 5, lane = threadIdx.x & 31, gr = lane >> 2, tg = lane & 3;
    const int wm = wid >> 2, wn = wid & 3;
    float* dst = g_S + (size_t)b * NPIX * NPIX;
    #pragma unroll
    for (int i = 0; i < 4; i++) {
        int row = m0 + wm * 64 + i * 16 + gr;
        #pragma unroll
        for (int j = 0; j < 4; j++) {
            int col = n0 + wn * 32 + j * 8 + tg * 2;
            *(float2*)&dst[(size_t)row * NPIX + col]       = make_float2(acc[i][j][0], acc[i][j][1]);
            *(float2*)&dst[(size_t)(row + 8) * NPIX + col] = make_float2(acc[i][j][2], acc[i][j][3]);
        }
    }
}

// ================= row softmax: S fp32 -> P bf16 =================
__global__ __launch_bounds__(256) void softmax_rows() {
    const float4* p = (const float4*)(g_S + (size_t)blockIdx.x * NPIX);
    bf16* q = g_P + (size_t)blockIdx.x * NPIX;
    const int t = threadIdx.x;
    float4 v = p[t];
    float mx = fmaxf(fmaxf(v.x, v.y), fmaxf(v.z, v.w));
    #pragma unroll
    for (int o = 16; o; o >>= 1) mx = fmaxf(mx, __shfl_xor_sync(~0u, mx, o));
    __shared__ float red[8];
    if ((t & 31) == 0) red[t >> 5] = mx;
    __syncthreads();
    mx = red[0];
    #pragma unroll
    for (int i = 1; i < 8; i++) mx = fmaxf(mx, red[i]);
    __syncthreads();
    v.x = __expf(v.x - mx); v.y = __expf(v.y - mx);
    v.z = __expf(v.z - mx); v.w = __expf(v.w - mx);
    float s = v.x + v.y + v.z + v.w;
    #pragma unroll
    for (int o = 16; o; o >>= 1) s += __shfl_xor_sync(~0u, s, o);
    if ((t & 31) == 0) red[t >> 5] = s;
    __syncthreads();
    s = 0.f;
    #pragma unroll
    for (int i = 0; i < 8; i++) s += red[i];
    float inv = 1.f / s;
    uint2 out;
    out.x = pk2(v.x * inv, v.y * inv);
    out.y = pk2(v.z * inv, v.w * inv);
    *(uint2*)&q[t * 4] = out;
}

// ========== O[n][c] = P[n,:]·v[c,:] -> g_out bf16 ==========
__global__ __launch_bounds__(256) void o_gemm() {
    const int b = blockIdx.z, m0 = blockIdx.y * 128, n0 = blockIdx.x * 128;
    float acc[4][4][4] = {};
    gemm_core<NPIX / BKC>(g_P + (size_t)b * NPIX * NPIX + (size_t)m0 * NPIX, NPIX,
                          g_v + (size_t)b * CH * NPIX + (size_t)n0 * NPIX, NPIX, acc);
    const int wid = threadIdx.x >> 5, lane = threadIdx.x & 31, gr = lane >> 2, tg = lane & 3;
    const int wm = wid >> 2, wn = wid & 3;
    bf16* dst = g_out + (size_t)b * NPIX * CH;
    #pragma unroll
    for (int i = 0; i < 4; i++) {
        int row = m0 + wm * 64 + i * 16 + gr;
        #pragma unroll
        for (int j = 0; j < 4; j++) {
            int col = n0 + wn * 32 + j * 8 + tg * 2;
            *(uint32_t*)&dst[(size_t)row * CH + col]       = pk2(acc[i][j][0], acc[i][j][1]);
            *(uint32_t*)&dst[(size_t)(row + 8) * CH + col] = pk2(acc[i][j][2], acc[i][j][3]);
        }
    }
}

// ========== proj: y[o][n] = x + pb[o] + Wp[o,:]·out[n,:] ==========
__global__ __launch_bounds__(256) void proj_gemm(const float* __restrict__ x,
                                                 const float* __restrict__ pb,
                                                 float* __restrict__ y) {
    const int b = blockIdx.z, m0 = blockIdx.y * 128, n0 = blockIdx.x * 128;
    float acc[4][4][4] = {};
    gemm_core<CH / BKC>(g_wp + (size_t)m0 * CH, CH,
                        g_out + (size_t)b * NPIX * CH + (size_t)n0 * CH, CH, acc);
    const int wid = threadIdx.x >> 5, lane = threadIdx.x & 31, gr = lane >> 2, tg = lane & 3;
    const int wm = wid >> 2, wn = wid & 3;
    const float* xb = x + (size_t)b * CH * NPIX;
    float* yb = y + (size_t)b * CH * NPIX;
    #pragma unroll
    for (int i = 0; i < 4; i++) {
        int row = m0 + wm * 64 + i * 16 + gr;
        float b0 = pb[row], b1 = pb[row + 8];
        #pragma unroll
        for (int j = 0; j < 4; j++) {
            int col = n0 + wn * 32 + j * 8 + tg * 2;
            size_t i0 = (size_t)row * NPIX + col;
            size_t i1 = (size_t)(row + 8) * NPIX + col;
            float2 x0 = *(const float2*)&xb[i0];
            float2 x1 = *(const float2*)&xb[i1];
            *(float2*)&yb[i0] = make_float2(x0.x + b0 + acc[i][j][0], x0.y + b0 + acc[i][j][1]);
            *(float2*)&yb[i1] = make_float2(x1.x + b1 + acc[i][j][2], x1.y + b1 + acc[i][j][3]);
        }
    }
}

extern "C" void kernel_launch(void* const* d_in, const int* in_sizes, int n_in,
                              void* d_out, int out_size) {
    const float* x      = (const float*)d_in[0];
    const float* norm_w = (const float*)d_in[1];
    const float* norm_b = (const float*)d_in[2];
    const float* qkv_w  = (const float*)d_in[3];
    const float* proj_w = (const float*)d_in[4];
    const float* proj_b = (const float*)d_in[5];
    float* y = (float*)d_out;

    static bool attr_done = false;
    if (!attr_done) {
        cudaFuncSetAttribute(qk_gemm,  cudaFuncAttributeMaxDynamicSharedMemorySize, SMEM_REQ);
        cudaFuncSetAttribute(v_gemm,   cudaFuncAttributeMaxDynamicSharedMemorySize, SMEM_REQ);
        cudaFuncSetAttribute(s_gemm,   cudaFuncAttributeMaxDynamicSharedMemorySize, SMEM_REQ);
        cudaFuncSetAttribute(o_gemm,   cudaFuncAttributeMaxDynamicSharedMemorySize, SMEM_REQ);
        cudaFuncSetAttribute(proj_gemm,cudaFuncAttributeMaxDynamicSharedMemorySize, SMEM_REQ);
        attr_done = true;
    }

    gn_stats<<<BATCH * GROUPS, 256>>>(x, norm_w, norm_b);
    wcvt<<<(1024 * CH) / (256 * 4), 256>>>(qkv_w, proj_w);
    ht_kernel<<<dim3(NPIX / 32, CH / 32, BATCH), 256>>>(x);
    qk_gemm<<<dim3(4, NPIX / 128, BATCH), 256, SMEM_REQ>>>();
    v_gemm<<<dim3(NPIX / 128, 2, BATCH), 256, SMEM_REQ>>>();
    s_gemm<<<dim3(NPIX / 128, NPIX / 128, BATCH), 256, SMEM_REQ>>>();
    softmax_rows<<<BATCH * NPIX, 256>>>();
    o_gemm<<<dim3(2, NPIX / 128, BATCH), 256, SMEM_REQ>>>();
    proj_gemm<<<dim3(NPIX / 128, 2, BATCH), 256, SMEM_REQ>>>(x, proj_b, y);
}

// round 5
// speedup vs baseline: 5.8124x; 1.1001x over previous
#include <cuda_runtime.h>
#include <cuda_bf16.h>
#include <stdint.h>

#define BATCH 32
#define CH    256
#define NPIX  1024
#define GROUPS 8
#define CPG   32
#define EPSV  1e-5f

#define BKC 32
#define TILE_B  8192                 // bytes per operand tile (128 rows x 64B)
#define STAGE_B (2 * TILE_B)
#define NSG 3
#define SMEM_REQ (NSG * STAGE_B)     // 49152 bytes

typedef __nv_bfloat16 bf16;

// ---- scratch (static device globals: allocation-free) ----
__device__ bf16 g_hT [(size_t)BATCH * NPIX * CH];    // [b][n][c]
__device__ bf16 g_qT [(size_t)BATCH * NPIX * CH];    // [b][n][c] (W_q pre-scaled 1/16)
__device__ bf16 g_kT [(size_t)BATCH * NPIX * CH];    // [b][m][c]
__device__ bf16 g_v  [(size_t)BATCH * CH * NPIX];    // [b][c][m]
__device__ bf16 g_out[(size_t)BATCH * NPIX * CH];    // [b][n][c]
__device__ float g_S [(size_t)BATCH * NPIX * NPIX];  // [b][n][m] fp32
__device__ bf16 g_P  [(size_t)BATCH * NPIX * NPIX];  // [b][n][m] probs
__device__ bf16 g_wqk[(size_t)512 * CH];
__device__ bf16 g_wv [(size_t)CH * CH];
__device__ bf16 g_wp [(size_t)CH * CH];
__device__ float g_scale[BATCH * CH];
__device__ float g_shift[BATCH * CH];

// ================= helpers =================
__device__ __forceinline__ uint32_t smem_u32(const void* p) {
    uint32_t a;
    asm("{ .reg .u64 t; cvta.to.shared.u64 t, %1; cvt.u32.u64 %0, t; }" : "=r"(a) : "l"(p));
    return a;
}
__device__ __forceinline__ void cpa16(uint32_t d, const void* s) {
    asm volatile("cp.async.cg.shared.global [%0], [%1], 16;" :: "r"(d), "l"(s));
}
__device__ __forceinline__ uint32_t pk2(float lo, float hi) {
    uint32_t r;
    asm("cvt.rn.bf16x2.f32 %0, %1, %2;" : "=r"(r) : "f"(hi), "f"(lo));
    return r;
}
__device__ __forceinline__ void mma_bf16(float c[4], const uint32_t a[4], uint32_t b0, uint32_t b1) {
    asm volatile("mma.sync.aligned.m16n8k16.row.col.f32.bf16.bf16.f32 "
                 "{%0,%1,%2,%3}, {%4,%5,%6,%7}, {%8,%9}, {%0,%1,%2,%3};\n"
                 : "+f"(c[0]), "+f"(c[1]), "+f"(c[2]), "+f"(c[3])
                 : "r"(a[0]), "r"(a[1]), "r"(a[2]), "r"(a[3]), "r"(b0), "r"(b1));
}
__device__ __forceinline__ void ldmx4(uint32_t r[4], uint32_t addr) {
    asm volatile("ldmatrix.sync.aligned.m8n8.x4.shared.b16 {%0,%1,%2,%3}, [%4];"
                 : "=r"(r[0]), "=r"(r[1]), "=r"(r[2]), "=r"(r[3]) : "r"(addr));
}
// swizzled byte offset for (row r in [0,128), 16B k-chunk kc in [0,4))
__device__ __forceinline__ uint32_t swz(uint32_t r, uint32_t kc) {
    uint32_t o = (r >> 1) * 128 + (r & 1) * 64 + kc * 16;
    return o ^ ((o >> 3) & 0x70);
}

// ====== bf16 mma.sync GEMM core: D[128,128] = A[128,K] (row) * B[128,K]^T ======
template <int NT>
__device__ __forceinline__ void gemm_core(const bf16* __restrict__ A, int lda,
                                          const bf16* __restrict__ B, int ldb,
                                          float (&acc)[4][4][4]) {
    extern __shared__ char sh[];
    const uint32_t sbase = smem_u32(sh);
    const int tid = threadIdx.x, lane = tid & 31, wid = tid >> 5;
    const int wm = wid >> 2, wn = wid & 3;
    const int dl  = (lane & 7) + ((lane >> 3) & 1) * 8;   // ldmatrix row offset
    const int dkc = lane >> 4;                             // ldmatrix chunk offset

    auto load_stage = [&](int s, int t) {
        uint32_t ab = sbase + s * STAGE_B;
        uint32_t bb = ab + TILE_B;
        const bf16* ga = A + t * BKC;
        const bf16* gb = B + t * BKC;
        #pragma unroll
        for (int it = 0; it < 2; it++) {
            int c = tid + it * 256;
            int r = c >> 2, kc = c & 3;
            uint32_t o = swz(r, kc);
            cpa16(ab + o, ga + (size_t)r * lda + kc * 8);
            cpa16(bb + o, gb + (size_t)r * ldb + kc * 8);
        }
        asm volatile("cp.async.commit_group;");
    };

    load_stage(0, 0);
    if (NT > 1) load_stage(1, 1);

    for (int t = 0; t < NT; t++) {
        if (t + 2 < NT) { load_stage((t + 2) % NSG, t + 2); asm volatile("cp.async.wait_group 2;"); }
        else if (t + 1 < NT) asm volatile("cp.async.wait_group 1;");
        else                 asm volatile("cp.async.wait_group 0;");
        __syncthreads();

        uint32_t ab = sbase + (t % NSG) * STAGE_B;
        uint32_t bb = ab + TILE_B;
        #pragma unroll
        for (int ks = 0; ks < 2; ks++) {
            uint32_t a[4][4], b2[2][4];
            #pragma unroll
            for (int i = 0; i < 4; i++)
                ldmx4(a[i], ab + swz(wm * 64 + i * 16 + dl, ks * 2 + dkc));
            #pragma unroll
            for (int jj = 0; jj < 2; jj++)
                ldmx4(b2[jj], bb + swz(wn * 32 + jj * 16 + dl, ks * 2 + dkc));
            #pragma unroll
            for (int i = 0; i < 4; i++)
                #pragma unroll
                for (int j = 0; j < 4; j++)
                    mma_bf16(acc[i][j], a[i], b2[j >> 1][j & 1], b2[j >> 1][(j & 1) + 2]);
        }
        __syncthreads();
    }
}

// ================= GroupNorm stats =================
__global__ __launch_bounds__(256) void gn_stats(const float* __restrict__ x,
                                                const float* __restrict__ nw,
                                                const float* __restrict__ nb) {
    int bg = blockIdx.x;
    int b = bg / GROUPS, g = bg % GROUPS;
    const float4* p4 = (const float4*)(x + ((size_t)b * CH + (size_t)g * CPG) * NPIX);
    float s = 0.f, sq = 0.f;
    for (int i = threadIdx.x; i < CPG * NPIX / 4; i += 256) {
        float4 v = p4[i];
        s += v.x + v.y + v.z + v.w;
        sq += v.x * v.x + v.y * v.y + v.z * v.z + v.w * v.w;
    }
    #pragma unroll
    for (int o = 16; o; o >>= 1) {
        s  += __shfl_xor_sync(~0u, s, o);
        sq += __shfl_xor_sync(~0u, sq, o);
    }
    __shared__ float ss[8], ssq[8];
    if ((threadIdx.x & 31) == 0) { ss[threadIdx.x >> 5] = s; ssq[threadIdx.x >> 5] = sq; }
    __syncthreads();
    if (threadIdx.x < CPG) {
        float st = 0.f, sqt = 0.f;
        #pragma unroll
        for (int i = 0; i < 8; i++) { st += ss[i]; sqt += ssq[i]; }
        const float inv_n = 1.f / (float)(CPG * NPIX);
        float mean = st * inv_n;
        float var  = sqt * inv_n - mean * mean;
        float rstd = rsqrtf(var + EPSV);
        int c = g * CPG + threadIdx.x;
        float sc = rstd * nw[c];
        g_scale[b * CH + c] = sc;
        g_shift[b * CH + c] = nb[c] - mean * sc;
    }
}

// ================= weights -> bf16 (q rows pre-scaled 1/16) =================
__global__ __launch_bounds__(256) void wcvt(const float* __restrict__ qkv_w,
                                            const float* __restrict__ proj_w) {
    int idx = blockIdx.x * 256 + threadIdx.x;
    #pragma unroll
    for (int u = 0; u < 4; u++) {
        int e = idx * 4 + u;
        if (e < 768 * CH) {
            int row = e / CH;
            float v = qkv_w[e];
            if (row < CH) v *= 0.0625f;
            if (row < 512) g_wqk[e] = __float2bfloat16(v);
            else           g_wv[e - 512 * CH] = __float2bfloat16(v);
        } else {
            int e2 = e - 768 * CH;
            g_wp[e2] = __float2bfloat16(proj_w[e2]);
        }
    }
}

// ================= normalize + transpose: hT[b][n][c] bf16 =================
__global__ __launch_bounds__(256) void ht_kernel(const float* __restrict__ x) {
    __shared__ float tile[32][33];
    int b = blockIdx.z, c0 = blockIdx.y * 32, n0 = blockIdx.x * 32;
    int tx = threadIdx.x & 31, ty = threadIdx.x >> 5;
    const float* xb = x + ((size_t)b * CH + c0) * NPIX;
    #pragma unroll
    for (int k = 0; k < 4; k++) {
        int c = ty + k * 8;
        float sc = g_scale[b * CH + c0 + c], sh = g_shift[b * CH + c0 + c];
        tile[c][tx] = fmaf(xb[(size_t)c * NPIX + n0 + tx], sc, sh);
    }
    __syncthreads();
    bf16* dst = g_hT + (size_t)b * NPIX * CH;
    #pragma unroll
    for (int k = 0; k < 4; k++) {
        int n = ty + k * 8;
        dst[(size_t)(n0 + n) * CH + c0 + tx] = __float2bfloat16(tile[tx][n]);
    }
}

// ========== QK: D[n][o] = hT[n,:]·Wqk[o,:],  o<256 -> qT, else -> kT ==========
__global__ __launch_bounds__(256) void qk_gemm() {
    const int b = blockIdx.z, m0 = blockIdx.y * 128, n0 = blockIdx.x * 128;
    float acc[4][4][4] = {};
    gemm_core<CH / BKC>(g_hT + (size_t)b * NPIX * CH + (size_t)m0 * CH, CH,
                        g_wqk + (size_t)n0 * CH, CH, acc);
    const int wid = threadIdx.x >> 5, lane = threadIdx.x & 31, gr = lane >> 2, tg = lane & 3;
    const int wm = wid >> 2, wn = wid & 3;
    bf16* dst = (n0 < 256 ? g_qT : g_kT) + (size_t)b * NPIX * CH;
    const int c0 = n0 & 255;
    #pragma unroll
    for (int i = 0; i < 4; i++) {
        int row = m0 + wm * 64 + i * 16 + gr;
        #pragma unroll
        for (int j = 0; j < 4; j++) {
            int col = c0 + wn * 32 + j * 8 + tg * 2;
            *(uint32_t*)&dst[(size_t)row * CH + col]       = pk2(acc[i][j][0], acc[i][j][1]);
            *(uint32_t*)&dst[(size_t)(row + 8) * CH + col] = pk2(acc[i][j][2], acc[i][j][3]);
        }
    }
}

// ========== V: D[c][m] = Wv[c,:]·hT[m,:] -> g_v[c][m] ==========
__global__ __launch_bounds__(256) void v_gemm() {
    const int b = blockIdx.z, m0 = blockIdx.y * 128, n0 = blockIdx.x * 128;
    float acc[4][4][4] = {};
    gemm_core<CH / BKC>(g_wv + (size_t)m0 * CH, CH,
                        g_hT + (size_t)b * NPIX * CH + (size_t)n0 * CH, CH, acc);
    const int wid = threadIdx.x >> 5, lane = threadIdx.x & 31, gr = lane >> 2, tg = lane & 3;
    const int wm = wid >> 2, wn = wid & 3;
    bf16* dst = g_v + (size_t)b * CH * NPIX;
    #pragma unroll
    for (int i = 0; i < 4; i++) {
        int row = m0 + wm * 64 + i * 16 + gr;
        #pragma unroll
        for (int j = 0; j < 4; j++) {
            int col = n0 + wn * 32 + j * 8 + tg * 2;
            *(uint32_t*)&dst[(size_t)row * NPIX + col]       = pk2(acc[i][j][0], acc[i][j][1]);
            *(uint32_t*)&dst[(size_t)(row + 8) * NPIX + col] = pk2(acc[i][j][2], acc[i][j][3]);
        }
    }
}

// ========== S[n][m] = qT[n,:]·kT[m,:]  (fp32 out) ==========
__global__ __launch_bounds__(256) void s_gemm() {
    const int b = blockIdx.z, m0 = blockIdx.y * 128, n0 = blockIdx.x * 128;
    float acc[4][4][4] = {};
    gemm_core<CH / BKC>(g_qT + (size_t)b * NPIX * CH + (size_t)m0 * CH, CH,
                        g_kT + (size_t)b * NPIX * CH + (size_t)n0 * CH, CH, acc);
    const int wid = threadIdx.x >> 5, lane = threadIdx.x & 31, gr = lane >> 2, tg = lane & 3;
    const int wm = wid >> 2, wn = wid & 3;
    float* dst = g_S + (size_t)b * NPIX * NPIX;
    #pragma unroll
    for (int i = 0; i < 4; i++) {
        int row = m0 + wm * 64 + i * 16 + gr;
        #pragma unroll
        for (int j = 0; j < 4; j++) {
            int col = n0 + wn * 32 + j * 8 + tg * 2;
            *(float2*)&dst[(size_t)row * NPIX + col]       = make_float2(acc[i][j][0], acc[i][j][1]);
            *(float2*)&dst[(size_t)(row + 8) * NPIX + col] = make_float2(acc[i][j][2], acc[i][j][3]);
        }
    }
}

// ================= row softmax: S fp32 -> P bf16 =================
__global__ __launch_bounds__(256) void softmax_rows() {
    const float4* p = (const float4*)(g_S + (size_t)blockIdx.x * NPIX);
    bf16* q = g_P + (size_t)blockIdx.x * NPIX;
    const int t = threadIdx.x;
    float4 v = p[t];
    float mx = fmaxf(fmaxf(v.x, v.y), fmaxf(v.z, v.w));
    #pragma unroll
    for (int o = 16; o; o >>= 1) mx = fmaxf(mx, __shfl_xor_sync(~0u, mx, o));
    __shared__ float red[8];
    if ((t & 31) == 0) red[t >> 5] = mx;
    __syncthreads();
    mx = red[0];
    #pragma unroll
    for (int i = 1; i < 8; i++) mx = fmaxf(mx, red[i]);
    __syncthreads();
    v.x = __expf(v.x - mx); v.y = __expf(v.y - mx);
    v.z = __expf(v.z - mx); v.w = __expf(v.w - mx);
    float s = v.x + v.y + v.z + v.w;
    #pragma unroll
    for (int o = 16; o; o >>= 1) s += __shfl_xor_sync(~0u, s, o);
    if ((t & 31) == 0) red[t >> 5] = s;
    __syncthreads();
    s = 0.f;
    #pragma unroll
    for (int i = 0; i < 8; i++) s += red[i];
    float inv = 1.f / s;
    uint2 out;
    out.x = pk2(v.x * inv, v.y * inv);
    out.y = pk2(v.z * inv, v.w * inv);
    *(uint2*)&q[t * 4] = out;
}

// ========== O[n][c] = P[n,:]·v[c,:] -> g_out bf16 ==========
__global__ __launch_bounds__(256) void o_gemm() {
    const int b = blockIdx.z, m0 = blockIdx.y * 128, n0 = blockIdx.x * 128;
    float acc[4][4][4] = {};
    gemm_core<NPIX / BKC>(g_P + (size_t)b * NPIX * NPIX + (size_t)m0 * NPIX, NPIX,
                          g_v + (size_t)b * CH * NPIX + (size_t)n0 * NPIX, NPIX, acc);
    const int wid = threadIdx.x >> 5, lane = threadIdx.x & 31, gr = lane >> 2, tg = lane & 3;
    const int wm = wid >> 2, wn = wid & 3;
    bf16* dst = g_out + (size_t)b * NPIX * CH;
    #pragma unroll
    for (int i = 0; i < 4; i++) {
        int row = m0 + wm * 64 + i * 16 + gr;
        #pragma unroll
        for (int j = 0; j < 4; j++) {
            int col = n0 + wn * 32 + j * 8 + tg * 2;
            *(uint32_t*)&dst[(size_t)row * CH + col]       = pk2(acc[i][j][0], acc[i][j][1]);
            *(uint32_t*)&dst[(size_t)(row + 8) * CH + col] = pk2(acc[i][j][2], acc[i][j][3]);
        }
    }
}

// ========== proj: y[o][n] = x + pb[o] + Wp[o,:]·out[n,:] ==========
__global__ __launch_bounds__(256) void proj_gemm(const float* __restrict__ x,
                                                 const float* __restrict__ pb,
                                                 float* __restrict__ y) {
    const int b = blockIdx.z, m0 = blockIdx.y * 128, n0 = blockIdx.x * 128;
    float acc[4][4][4] = {};
    gemm_core<CH / BKC>(g_wp + (size_t)m0 * CH, CH,
                        g_out + (size_t)b * NPIX * CH + (size_t)n0 * CH, CH, acc);
    const int wid = threadIdx.x >> 5, lane = threadIdx.x & 31, gr = lane >> 2, tg = lane & 3;
    const int wm = wid >> 2, wn = wid & 3;
    const float* xb = x + (size_t)b * CH * NPIX;
    float* yb = y + (size_t)b * CH * NPIX;
    #pragma unroll
    for (int i = 0; i < 4; i++) {
        int row = m0 + wm * 64 + i * 16 + gr;
        float b0 = pb[row], b1 = pb[row + 8];
        #pragma unroll
        for (int j = 0; j < 4; j++) {
            int col = n0 + wn * 32 + j * 8 + tg * 2;
            size_t i0 = (size_t)row * NPIX + col;
            size_t i1 = (size_t)(row + 8) * NPIX + col;
            float2 x0 = *(const float2*)&xb[i0];
            float2 x1 = *(const float2*)&xb[i1];
            *(float2*)&yb[i0] = make_float2(x0.x + b0 + acc[i][j][0], x0.y + b0 + acc[i][j][1]);
            *(float2*)&yb[i1] = make_float2(x1.x + b1 + acc[i][j][2], x1.y + b1 + acc[i][j][3]);
        }
    }
}

extern "C" void kernel_launch(void* const* d_in, const int* in_sizes, int n_in,
                              void* d_out, int out_size) {
    const float* x      = (const float*)d_in[0];
    const float* norm_w = (const float*)d_in[1];
    const float* norm_b = (const float*)d_in[2];
    const float* qkv_w  = (const float*)d_in[3];
    const float* proj_w = (const float*)d_in[4];
    const float* proj_b = (const float*)d_in[5];
    float* y = (float*)d_out;

    cudaFuncSetAttribute(qk_gemm,   cudaFuncAttributeMaxDynamicSharedMemorySize, SMEM_REQ);
    cudaFuncSetAttribute(v_gemm,    cudaFuncAttributeMaxDynamicSharedMemorySize, SMEM_REQ);
    cudaFuncSetAttribute(s_gemm,    cudaFuncAttributeMaxDynamicSharedMemorySize, SMEM_REQ);
    cudaFuncSetAttribute(o_gemm,    cudaFuncAttributeMaxDynamicSharedMemorySize, SMEM_REQ);
    cudaFuncSetAttribute(proj_gemm, cudaFuncAttributeMaxDynamicSharedMemorySize, SMEM_REQ);

    gn_stats<<<BATCH * GROUPS, 256>>>(x, norm_w, norm_b);
    wcvt<<<(1024 * CH) / (256 * 4), 256>>>(qkv_w, proj_w);
    ht_kernel<<<dim3(NPIX / 32, CH / 32, BATCH), 256>>>(x);
    qk_gemm<<<dim3(4, NPIX / 128, BATCH), 256, SMEM_REQ>>>();
    v_gemm<<<dim3(NPIX / 128, 2, BATCH), 256, SMEM_REQ>>>();
    s_gemm<<<dim3(NPIX / 128, NPIX / 128, BATCH), 256, SMEM_REQ>>>();
    softmax_rows<<<BATCH * NPIX, 256>>>();
    o_gemm<<<dim3(2, NPIX / 128, BATCH), 256, SMEM_REQ>>>();
    proj_gemm<<<dim3(NPIX / 128, 2, BATCH), 256, SMEM_REQ>>>(x, proj_b, y);
}

// round 6
// speedup vs baseline: 6.0135x; 1.0346x over previous
#include <cuda_runtime.h>
#include <cuda_bf16.h>
#include <stdint.h>

#define BATCH 32
#define CH    256
#define NPIX  1024
#define GROUPS 8
#define CPG   32
#define EPSV  1e-5f

#define BKC 32
#define TILE_B  8192                 // bytes per operand tile (128 rows x 64B)
#define STAGE_B (2 * TILE_B)
#define NSG 3
#define SMEM_REQ (NSG * STAGE_B)     // 49152 bytes

typedef __nv_bfloat16 bf16;

// ---- scratch (static device globals: allocation-free) ----
__device__ bf16 g_hT [(size_t)BATCH * NPIX * CH];    // [b][n][c]
__device__ bf16 g_qT [(size_t)BATCH * NPIX * CH];    // [b][n][c] (W_q pre-scaled 1/16)
__device__ bf16 g_kT [(size_t)BATCH * NPIX * CH];    // [b][m][c]
__device__ bf16 g_v  [(size_t)BATCH * CH * NPIX];    // [b][c][m]
__device__ bf16 g_out[(size_t)BATCH * NPIX * CH];    // [b][n][c]
__device__ float g_S [(size_t)BATCH * NPIX * NPIX];  // [b][n][m] fp32
__device__ bf16 g_P  [(size_t)BATCH * NPIX * NPIX];  // [b][n][m] probs
__device__ bf16 g_wqk[(size_t)512 * CH];
__device__ bf16 g_wv [(size_t)CH * CH];
__device__ bf16 g_wp [(size_t)CH * CH];
__device__ float g_scale[BATCH * CH];
__device__ float g_shift[BATCH * CH];

// ================= helpers =================
__device__ __forceinline__ uint32_t smem_u32(const void* p) {
    uint32_t a;
    asm("{ .reg .u64 t; cvta.to.shared.u64 t, %1; cvt.u32.u64 %0, t; }" : "=r"(a) : "l"(p));
    return a;
}
__device__ __forceinline__ void cpa16(uint32_t d, const void* s) {
    asm volatile("cp.async.cg.shared.global [%0], [%1], 16;" :: "r"(d), "l"(s));
}
__device__ __forceinline__ uint32_t pk2(float lo, float hi) {
    uint32_t r;
    asm("cvt.rn.bf16x2.f32 %0, %1, %2;" : "=r"(r) : "f"(hi), "f"(lo));
    return r;
}
__device__ __forceinline__ void mma_bf16(float c[4], const uint32_t a[4], uint32_t b0, uint32_t b1) {
    asm volatile("mma.sync.aligned.m16n8k16.row.col.f32.bf16.bf16.f32 "
                 "{%0,%1,%2,%3}, {%4,%5,%6,%7}, {%8,%9}, {%0,%1,%2,%3};\n"
                 : "+f"(c[0]), "+f"(c[1]), "+f"(c[2]), "+f"(c[3])
                 : "r"(a[0]), "r"(a[1]), "r"(a[2]), "r"(a[3]), "r"(b0), "r"(b1));
}
__device__ __forceinline__ void ldmx4(uint32_t r[4], uint32_t addr) {
    asm volatile("ldmatrix.sync.aligned.m8n8.x4.shared.b16 {%0,%1,%2,%3}, [%4];"
                 : "=r"(r[0]), "=r"(r[1]), "=r"(r[2]), "=r"(r[3]) : "r"(addr));
}
// swizzled byte offset for (row r in [0,128), 16B k-chunk kc in [0,4))
__device__ __forceinline__ uint32_t swz(uint32_t r, uint32_t kc) {
    uint32_t o = (r >> 1) * 128 + (r & 1) * 64 + kc * 16;
    return o ^ ((o >> 3) & 0x70);
}

// ====== bf16 mma.sync GEMM core: D[128,128] = A[128,K] (row) * B[128,K]^T ======
// 128 threads, warps 2x2, warp tile 64x64. acc[4][8][4].
template <int NT>
__device__ __forceinline__ void gemm_core(const bf16* __restrict__ A, int lda,
                                          const bf16* __restrict__ B, int ldb,
                                          float (&acc)[4][8][4]) {
    extern __shared__ char sh[];
    const uint32_t sbase = smem_u32(sh);
    const int tid = threadIdx.x, lane = tid & 31, wid = tid >> 5;
    const int wm = wid >> 1, wn = wid & 1;
    const int dl  = (lane & 7) + ((lane >> 3) & 1) * 8;   // ldmatrix row offset
    const int dkc = lane >> 4;                             // ldmatrix chunk offset

    auto load_stage = [&](int s, int t) {
        uint32_t ab = sbase + s * STAGE_B;
        uint32_t bb = ab + TILE_B;
        const bf16* ga = A + t * BKC;
        const bf16* gb = B + t * BKC;
        #pragma unroll
        for (int it = 0; it < 4; it++) {
            int c = tid + it * 128;
            int r = c >> 2, kc = c & 3;
            uint32_t o = swz(r, kc);
            cpa16(ab + o, ga + (size_t)r * lda + kc * 8);
            cpa16(bb + o, gb + (size_t)r * ldb + kc * 8);
        }
        asm volatile("cp.async.commit_group;");
    };

    load_stage(0, 0);
    if (NT > 1) load_stage(1, 1);

    for (int t = 0; t < NT; t++) {
        if (t + 2 < NT) { load_stage((t + 2) % NSG, t + 2); asm volatile("cp.async.wait_group 2;"); }
        else if (t + 1 < NT) asm volatile("cp.async.wait_group 1;");
        else                 asm volatile("cp.async.wait_group 0;");
        __syncthreads();

        uint32_t ab = sbase + (t % NSG) * STAGE_B;
        uint32_t bb = ab + TILE_B;
        #pragma unroll
        for (int ks = 0; ks < 2; ks++) {
            uint32_t a[4][4], b2[4][4];
            #pragma unroll
            for (int i = 0; i < 4; i++)
                ldmx4(a[i], ab + swz(wm * 64 + i * 16 + dl, ks * 2 + dkc));
            #pragma unroll
            for (int jj = 0; jj < 4; jj++)
                ldmx4(b2[jj], bb + swz(wn * 64 + jj * 16 + dl, ks * 2 + dkc));
            #pragma unroll
            for (int i = 0; i < 4; i++)
                #pragma unroll
                for (int j = 0; j < 8; j++)
                    mma_bf16(acc[i][j], a[i], b2[j >> 1][j & 1], b2[j >> 1][(j & 1) + 2]);
        }
        __syncthreads();
    }
}

// ================= GroupNorm stats =================
__global__ __launch_bounds__(256) void gn_stats(const float* __restrict__ x,
                                                const float* __restrict__ nw,
                                                const float* __restrict__ nb) {
    int bg = blockIdx.x;
    int b = bg / GROUPS, g = bg % GROUPS;
    const float4* p4 = (const float4*)(x + ((size_t)b * CH + (size_t)g * CPG) * NPIX);
    float s = 0.f, sq = 0.f;
    for (int i = threadIdx.x; i < CPG * NPIX / 4; i += 256) {
        float4 v = p4[i];
        s += v.x + v.y + v.z + v.w;
        sq += v.x * v.x + v.y * v.y + v.z * v.z + v.w * v.w;
    }
    #pragma unroll
    for (int o = 16; o; o >>= 1) {
        s  += __shfl_xor_sync(~0u, s, o);
        sq += __shfl_xor_sync(~0u, sq, o);
    }
    __shared__ float ss[8], ssq[8];
    if ((threadIdx.x & 31) == 0) { ss[threadIdx.x >> 5] = s; ssq[threadIdx.x >> 5] = sq; }
    __syncthreads();
    if (threadIdx.x < CPG) {
        float st = 0.f, sqt = 0.f;
        #pragma unroll
        for (int i = 0; i < 8; i++) { st += ss[i]; sqt += ssq[i]; }
        const float inv_n = 1.f / (float)(CPG * NPIX);
        float mean = st * inv_n;
        float var  = sqt * inv_n - mean * mean;
        float rstd = rsqrtf(var + EPSV);
        int c = g * CPG + threadIdx.x;
        float sc = rstd * nw[c];
        g_scale[b * CH + c] = sc;
        g_shift[b * CH + c] = nb[c] - mean * sc;
    }
}

// ================= weights -> bf16 (q rows pre-scaled 1/16) =================
__global__ __launch_bounds__(256) void wcvt(const float* __restrict__ qkv_w,
                                            const float* __restrict__ proj_w) {
    int idx = blockIdx.x * 256 + threadIdx.x;
    #pragma unroll
    for (int u = 0; u < 4; u++) {
        int e = idx * 4 + u;
        if (e < 768 * CH) {
            int row = e / CH;
            float v = qkv_w[e];
            if (row < CH) v *= 0.0625f;
            if (row < 512) g_wqk[e] = __float2bfloat16(v);
            else           g_wv[e - 512 * CH] = __float2bfloat16(v);
        } else {
            int e2 = e - 768 * CH;
            g_wp[e2] = __float2bfloat16(proj_w[e2]);
        }
    }
}

// ================= normalize + transpose: hT[b][n][c] bf16 =================
__global__ __launch_bounds__(256) void ht_kernel(const float* __restrict__ x) {
    __shared__ float tile[32][33];
    int b = blockIdx.z, c0 = blockIdx.y * 32, n0 = blockIdx.x * 32;
    int tx = threadIdx.x & 31, ty = threadIdx.x >> 5;
    const float* xb = x + ((size_t)b * CH + c0) * NPIX;
    #pragma unroll
    for (int k = 0; k < 4; k++) {
        int c = ty + k * 8;
        float sc = g_scale[b * CH + c0 + c], sh = g_shift[b * CH + c0 + c];
        tile[c][tx] = fmaf(xb[(size_t)c * NPIX + n0 + tx], sc, sh);
    }
    __syncthreads();
    bf16* dst = g_hT + (size_t)b * NPIX * CH;
    #pragma unroll
    for (int k = 0; k < 4; k++) {
        int n = ty + k * 8;
        dst[(size_t)(n0 + n) * CH + c0 + tx] = __float2bfloat16(tile[tx][n]);
    }
}

// ========== QK: D[n][o] = hT[n,:]·Wqk[o,:],  o<256 -> qT, else -> kT ==========
__global__ __launch_bounds__(128, 2) void qk_gemm() {
    const int b = blockIdx.z, m0 = blockIdx.y * 128, n0 = blockIdx.x * 128;
    float acc[4][8][4] = {};
    gemm_core<CH / BKC>(g_hT + (size_t)b * NPIX * CH + (size_t)m0 * CH, CH,
                        g_wqk + (size_t)n0 * CH, CH, acc);
    const int wid = threadIdx.x >> 5, lane = threadIdx.x & 31, gr = lane >> 2, tg = lane & 3;
    const int wm = wid >> 1, wn = wid & 1;
    bf16* dst = (n0 < 256 ? g_qT : g_kT) + (size_t)b * NPIX * CH;
    const int c0 = n0 & 255;
    #pragma unroll
    for (int i = 0; i < 4; i++) {
        int row = m0 + wm * 64 + i * 16 + gr;
        #pragma unroll
        for (int j = 0; j < 8; j++) {
            int col = c0 + wn * 64 + j * 8 + tg * 2;
            *(uint32_t*)&dst[(size_t)row * CH + col]       = pk2(acc[i][j][0], acc[i][j][1]);
            *(uint32_t*)&dst[(size_t)(row + 8) * CH + col] = pk2(acc[i][j][2], acc[i][j][3]);
        }
    }
}

// ========== V: D[c][m] = Wv[c,:]·hT[m,:] -> g_v[c][m] ==========
__global__ __launch_bounds__(128, 2) void v_gemm() {
    const int b = blockIdx.z, m0 = blockIdx.y * 128, n0 = blockIdx.x * 128;
    float acc[4][8][4] = {};
    gemm_core<CH / BKC>(g_wv + (size_t)m0 * CH, CH,
                        g_hT + (size_t)b * NPIX * CH + (size_t)n0 * CH, CH, acc);
    const int wid = threadIdx.x >> 5, lane = threadIdx.x & 31, gr = lane >> 2, tg = lane & 3;
    const int wm = wid >> 1, wn = wid & 1;
    bf16* dst = g_v + (size_t)b * CH * NPIX;
    #pragma unroll
    for (int i = 0; i < 4; i++) {
        int row = m0 + wm * 64 + i * 16 + gr;
        #pragma unroll
        for (int j = 0; j < 8; j++) {
            int col = n0 + wn * 64 + j * 8 + tg * 2;
            *(uint32_t*)&dst[(size_t)row * NPIX + col]       = pk2(acc[i][j][0], acc[i][j][1]);
            *(uint32_t*)&dst[(size_t)(row + 8) * NPIX + col] = pk2(acc[i][j][2], acc[i][j][3]);
        }
    }
}

// ========== S[n][m] = qT[n,:]·kT[m,:]  (fp32 out) ==========
__global__ __launch_bounds__(128, 2) void s_gemm() {
    const int b = blockIdx.z, m0 = blockIdx.y * 128, n0 = blockIdx.x * 128;
    float acc[4][8][4] = {};
    gemm_core<CH / BKC>(g_qT + (size_t)b * NPIX * CH + (size_t)m0 * CH, CH,
                        g_kT + (size_t)b * NPIX * CH + (size_t)n0 * CH, CH, acc);
    const int wid = threadIdx.x >> 5, lane = threadIdx.x & 31, gr = lane >> 2, tg = lane & 3;
    const int wm = wid >> 1, wn = wid & 1;
    float* dst = g_S + (size_t)b * NPIX * NPIX;
    #pragma unroll
    for (int i = 0; i < 4; i++) {
        int row = m0 + wm * 64 + i * 16 + gr;
        #pragma unroll
        for (int j = 0; j < 8; j++) {
            int col = n0 + wn * 64 + j * 8 + tg * 2;
            *(float2*)&dst[(size_t)row * NPIX + col]       = make_float2(acc[i][j][0], acc[i][j][1]);
            *(float2*)&dst[(size_t)(row + 8) * NPIX + col] = make_float2(acc[i][j][2], acc[i][j][3]);
        }
    }
}

// ================= row softmax: S fp32 -> P bf16 =================
__global__ __launch_bounds__(256) void softmax_rows() {
    const float4* p = (const float4*)(g_S + (size_t)blockIdx.x * NPIX);
    bf16* q = g_P + (size_t)blockIdx.x * NPIX;
    const int t = threadIdx.x;
    float4 v = p[t];
    float mx = fmaxf(fmaxf(v.x, v.y), fmaxf(v.z, v.w));
    #pragma unroll
    for (int o = 16; o; o >>= 1) mx = fmaxf(mx, __shfl_xor_sync(~0u, mx, o));
    __shared__ float red[8];
    if ((t & 31) == 0) red[t >> 5] = mx;
    __syncthreads();
    mx = red[0];
    #pragma unroll
    for (int i = 1; i < 8; i++) mx = fmaxf(mx, red[i]);
    __syncthreads();
    v.x = __expf(v.x - mx); v.y = __expf(v.y - mx);
    v.z = __expf(v.z - mx); v.w = __expf(v.w - mx);
    float s = v.x + v.y + v.z + v.w;
    #pragma unroll
    for (int o = 16; o; o >>= 1) s += __shfl_xor_sync(~0u, s, o);
    if ((t & 31) == 0) red[t >> 5] = s;
    __syncthreads();
    s = 0.f;
    #pragma unroll
    for (int i = 0; i < 8; i++) s += red[i];
    float inv = 1.f / s;
    uint2 out;
    out.x = pk2(v.x * inv, v.y * inv);
    out.y = pk2(v.z * inv, v.w * inv);
    *(uint2*)&q[t * 4] = out;
}

// ========== O[n][c] = P[n,:]·v[c,:] -> g_out bf16 ==========
__global__ __launch_bounds__(128, 2) void o_gemm() {
    const int b = blockIdx.z, m0 = blockIdx.y * 128, n0 = blockIdx.x * 128;
    float acc[4][8][4] = {};
    gemm_core<NPIX / BKC>(g_P + (size_t)b * NPIX * NPIX + (size_t)m0 * NPIX, NPIX,
                          g_v + (size_t)b * CH * NPIX + (size_t)n0 * NPIX, NPIX, acc);
    const int wid = threadIdx.x >> 5, lane = threadIdx.x & 31, gr = lane >> 2, tg = lane & 3;
    const int wm = wid >> 1, wn = wid & 1;
    bf16* dst = g_out + (size_t)b * NPIX * CH;
    #pragma unroll
    for (int i = 0; i < 4; i++) {
        int row = m0 + wm * 64 + i * 16 + gr;
        #pragma unroll
        for (int j = 0; j < 8; j++) {
            int col = n0 + wn * 64 + j * 8 + tg * 2;
            *(uint32_t*)&dst[(size_t)row * CH + col]       = pk2(acc[i][j][0], acc[i][j][1]);
            *(uint32_t*)&dst[(size_t)(row + 8) * CH + col] = pk2(acc[i][j][2], acc[i][j][3]);
        }
    }
}

// ========== proj: y[o][n] = x + pb[o] + Wp[o,:]·out[n,:] ==========
__global__ __launch_bounds__(128, 2) void proj_gemm(const float* __restrict__ x,
                                                    const float* __restrict__ pb,
                                                    float* __restrict__ y) {
    const int b = blockIdx.z, m0 = blockIdx.y * 128, n0 = blockIdx.x * 128;
    float acc[4][8][4] = {};
    gemm_core<CH / BKC>(g_wp + (size_t)m0 * CH, CH,
                        g_out + (size_t)b * NPIX * CH + (size_t)n0 * CH, CH, acc);
    const int wid = threadIdx.x >> 5, lane = threadIdx.x & 31, gr = lane >> 2, tg = lane & 3;
    const int wm = wid >> 1, wn = wid & 1;
    const float* xb = x + (size_t)b * CH * NPIX;
    float* yb = y + (size_t)b * CH * NPIX;
    #pragma unroll
    for (int i = 0; i < 4; i++) {
        int row = m0 + wm * 64 + i * 16 + gr;
        float b0 = pb[row], b1 = pb[row + 8];
        #pragma unroll
        for (int j = 0; j < 8; j++) {
            int col = n0 + wn * 64 + j * 8 + tg * 2;
            size_t i0 = (size_t)row * NPIX + col;
            size_t i1 = (size_t)(row + 8) * NPIX + col;
            float2 x0 = *(const float2*)&xb[i0];
            float2 x1 = *(const float2*)&xb[i1];
            *(float2*)&yb[i0] = make_float2(x0.x + b0 + acc[i][j][0], x0.y + b0 + acc[i][j][1]);
            *(float2*)&yb[i1] = make_float2(x1.x + b1 + acc[i][j][2], x1.y + b1 + acc[i][j][3]);
        }
    }
}

extern "C" void kernel_launch(void* const* d_in, const int* in_sizes, int n_in,
                              void* d_out, int out_size) {
    const float* x      = (const float*)d_in[0];
    const float* norm_w = (const float*)d_in[1];
    const float* norm_b = (const float*)d_in[2];
    const float* qkv_w  = (const float*)d_in[3];
    const float* proj_w = (const float*)d_in[4];
    const float* proj_b = (const float*)d_in[5];
    float* y = (float*)d_out;

    cudaFuncSetAttribute(qk_gemm,   cudaFuncAttributeMaxDynamicSharedMemorySize, SMEM_REQ);
    cudaFuncSetAttribute(v_gemm,    cudaFuncAttributeMaxDynamicSharedMemorySize, SMEM_REQ);
    cudaFuncSetAttribute(s_gemm,    cudaFuncAttributeMaxDynamicSharedMemorySize, SMEM_REQ);
    cudaFuncSetAttribute(o_gemm,    cudaFuncAttributeMaxDynamicSharedMemorySize, SMEM_REQ);
    cudaFuncSetAttribute(proj_gemm, cudaFuncAttributeMaxDynamicSharedMemorySize, SMEM_REQ);

    gn_stats<<<BATCH * GROUPS, 256>>>(x, norm_w, norm_b);
    wcvt<<<(1024 * CH) / (256 * 4), 256>>>(qkv_w, proj_w);
    ht_kernel<<<dim3(NPIX / 32, CH / 32, BATCH), 256>>>(x);
    qk_gemm<<<dim3(4, NPIX / 128, BATCH), 128, SMEM_REQ>>>();
    v_gemm<<<dim3(NPIX / 128, 2, BATCH), 128, SMEM_REQ>>>();
    s_gemm<<<dim3(NPIX / 128, NPIX / 128, BATCH), 128, SMEM_REQ>>>();
    softmax_rows<<<BATCH * NPIX, 256>>>();
    o_gemm<<<dim3(2, NPIX / 128, BATCH), 128, SMEM_REQ>>>();
    proj_gemm<<<dim3(NPIX / 128, 2, BATCH), 128, SMEM_REQ>>>(x, proj_b, y);
}

// round 7
// speedup vs baseline: 6.4465x; 1.0720x over previous
#include <cuda_runtime.h>
#include <cuda_bf16.h>
#include <stdint.h>

#define BATCH 32
#define CH    256
#define NPIX  1024
#define GROUPS 8
#define CPG   32
#define EPSV  1e-5f

#define BKC 64
#define TILE_B  16384                // bytes per operand tile (128 rows x 128B)
#define STAGE_B (2 * TILE_B)
#define NSG 3
#define SMEM_REQ (NSG * STAGE_B)     // 98304 bytes

typedef __nv_bfloat16 bf16;

// ---- scratch (static device globals: allocation-free) ----
__device__ bf16 g_hT [(size_t)BATCH * NPIX * CH];    // [b][n][c]
__device__ bf16 g_qT [(size_t)BATCH * NPIX * CH];    // [b][n][c] (W_q pre-scaled 1/16)
__device__ bf16 g_kT [(size_t)BATCH * NPIX * CH];    // [b][m][c]
__device__ bf16 g_v  [(size_t)BATCH * CH * NPIX];    // [b][c][m]
__device__ bf16 g_out[(size_t)BATCH * NPIX * CH];    // [b][n][c]
__device__ float g_S [(size_t)BATCH * NPIX * NPIX];  // [b][n][m] fp32
__device__ bf16 g_P  [(size_t)BATCH * NPIX * NPIX];  // [b][n][m] probs
__device__ bf16 g_wqk[(size_t)512 * CH];
__device__ bf16 g_wv [(size_t)CH * CH];
__device__ bf16 g_wp [(size_t)CH * CH];
__device__ float g_scale[BATCH * CH];
__device__ float g_shift[BATCH * CH];

// ================= helpers =================
__device__ __forceinline__ uint32_t smem_u32(const void* p) {
    uint32_t a;
    asm("{ .reg .u64 t; cvta.to.shared.u64 t, %1; cvt.u32.u64 %0, t; }" : "=r"(a) : "l"(p));
    return a;
}
__device__ __forceinline__ void cpa16(uint32_t d, const void* s) {
    asm volatile("cp.async.cg.shared.global [%0], [%1], 16;" :: "r"(d), "l"(s));
}
__device__ __forceinline__ uint32_t pk2(float lo, float hi) {
    uint32_t r;
    asm("cvt.rn.bf16x2.f32 %0, %1, %2;" : "=r"(r) : "f"(hi), "f"(lo));
    return r;
}
__device__ __forceinline__ void mma_bf16(float c[4], const uint32_t a[4], uint32_t b0, uint32_t b1) {
    asm volatile("mma.sync.aligned.m16n8k16.row.col.f32.bf16.bf16.f32 "
                 "{%0,%1,%2,%3}, {%4,%5,%6,%7}, {%8,%9}, {%0,%1,%2,%3};\n"
                 : "+f"(c[0]), "+f"(c[1]), "+f"(c[2]), "+f"(c[3])
                 : "r"(a[0]), "r"(a[1]), "r"(a[2]), "r"(a[3]), "r"(b0), "r"(b1));
}
__device__ __forceinline__ void ldmx4(uint32_t r[4], uint32_t addr) {
    asm volatile("ldmatrix.sync.aligned.m8n8.x4.shared.b16 {%0,%1,%2,%3}, [%4];"
                 : "=r"(r[0]), "=r"(r[1]), "=r"(r[2]), "=r"(r[3]) : "r"(addr));
}
// swizzled byte offset: row r in [0,128) (128B rows), 16B k-chunk kc in [0,8)
__device__ __forceinline__ uint32_t swz(uint32_t r, uint32_t kc) {
    return r * 128 + ((kc ^ (r & 7)) << 4);
}

// ====== bf16 mma.sync GEMM core: D[128,128] = A[128,K] (row) * B[128,K]^T ======
// 128 threads, warps 2x2, warp tile 64x64. acc[4][8][4]. BKC=64, 3-stage,
// ONE __syncthreads per k-tile (load for t+2 issued after the barrier).
template <int NT>
__device__ __forceinline__ void gemm_core(const bf16* __restrict__ A, int lda,
                                          const bf16* __restrict__ B, int ldb,
                                          float (&acc)[4][8][4]) {
    extern __shared__ char sh[];
    const uint32_t sbase = smem_u32(sh);
    const int tid = threadIdx.x, lane = tid & 31, wid = tid >> 5;
    const int wm = wid >> 1, wn = wid & 1;
    const int dl  = (lane & 7) + ((lane >> 3) & 1) * 8;   // ldmatrix row offset
    const int dkc = lane >> 4;                             // ldmatrix chunk offset

    auto load_stage = [&](int s, int t) {
        uint32_t ab = sbase + s * STAGE_B;
        uint32_t bb = ab + TILE_B;
        const bf16* ga = A + t * BKC;
        const bf16* gb = B + t * BKC;
        #pragma unroll
        for (int it = 0; it < 8; it++) {
            int c = tid + it * 128;
            int r = c >> 3, kc = c & 7;
            uint32_t o = swz(r, kc);
            cpa16(ab + o, ga + (size_t)r * lda + kc * 8);
            cpa16(bb + o, gb + (size_t)r * ldb + kc * 8);
        }
        asm volatile("cp.async.commit_group;");
    };

    load_stage(0, 0);
    if (NT > 1) load_stage(1, 1);

    #pragma unroll 1
    for (int t = 0; t < NT; t++) {
        // ensure group t complete (groups finish in order)
        if (t + 1 < NT) asm volatile("cp.async.wait_group 1;");
        else            asm volatile("cp.async.wait_group 0;");
        __syncthreads();   // all warps done reading buffer (t-1)%3 -> safe to overwrite
        if (t + 2 < NT) load_stage((t + 2) % NSG, t + 2);

        uint32_t ab = sbase + (t % NSG) * STAGE_B;
        uint32_t bb = ab + TILE_B;
        #pragma unroll
        for (int ks = 0; ks < 4; ks++) {
            uint32_t a[4][4], b2[4][4];
            #pragma unroll
            for (int i = 0; i < 4; i++)
                ldmx4(a[i], ab + swz(wm * 64 + i * 16 + dl, ks * 2 + dkc));
            #pragma unroll
            for (int jj = 0; jj < 4; jj++)
                ldmx4(b2[jj], bb + swz(wn * 64 + jj * 16 + dl, ks * 2 + dkc));
            #pragma unroll
            for (int i = 0; i < 4; i++)
                #pragma unroll
                for (int j = 0; j < 8; j++)
                    mma_bf16(acc[i][j], a[i], b2[j >> 1][j & 1], b2[j >> 1][(j & 1) + 2]);
        }
    }
}

// ================= GroupNorm stats =================
__global__ __launch_bounds__(256) void gn_stats(const float* __restrict__ x,
                                                const float* __restrict__ nw,
                                                const float* __restrict__ nb) {
    int bg = blockIdx.x;
    int b = bg / GROUPS, g = bg % GROUPS;
    const float4* p4 = (const float4*)(x + ((size_t)b * CH + (size_t)g * CPG) * NPIX);
    float s = 0.f, sq = 0.f;
    for (int i = threadIdx.x; i < CPG * NPIX / 4; i += 256) {
        float4 v = p4[i];
        s += v.x + v.y + v.z + v.w;
        sq += v.x * v.x + v.y * v.y + v.z * v.z + v.w * v.w;
    }
    #pragma unroll
    for (int o = 16; o; o >>= 1) {
        s  += __shfl_xor_sync(~0u, s, o);
        sq += __shfl_xor_sync(~0u, sq, o);
    }
    __shared__ float ss[8], ssq[8];
    if ((threadIdx.x & 31) == 0) { ss[threadIdx.x >> 5] = s; ssq[threadIdx.x >> 5] = sq; }
    __syncthreads();
    if (threadIdx.x < CPG) {
        float st = 0.f, sqt = 0.f;
        #pragma unroll
        for (int i = 0; i < 8; i++) { st += ss[i]; sqt += ssq[i]; }
        const float inv_n = 1.f / (float)(CPG * NPIX);
        float mean = st * inv_n;
        float var  = sqt * inv_n - mean * mean;
        float rstd = rsqrtf(var + EPSV);
        int c = g * CPG + threadIdx.x;
        float sc = rstd * nw[c];
        g_scale[b * CH + c] = sc;
        g_shift[b * CH + c] = nb[c] - mean * sc;
    }
}

// ================= weights -> bf16 (q rows pre-scaled 1/16) =================
__global__ __launch_bounds__(256) void wcvt(const float* __restrict__ qkv_w,
                                            const float* __restrict__ proj_w) {
    int idx = blockIdx.x * 256 + threadIdx.x;
    #pragma unroll
    for (int u = 0; u < 4; u++) {
        int e = idx * 4 + u;
        if (e < 768 * CH) {
            int row = e / CH;
            float v = qkv_w[e];
            if (row < CH) v *= 0.0625f;
            if (row < 512) g_wqk[e] = __float2bfloat16(v);
            else           g_wv[e - 512 * CH] = __float2bfloat16(v);
        } else {
            int e2 = e - 768 * CH;
            g_wp[e2] = __float2bfloat16(proj_w[e2]);
        }
    }
}

// ================= normalize + transpose: hT[b][n][c] bf16 =================
__global__ __launch_bounds__(256) void ht_kernel(const float* __restrict__ x) {
    __shared__ float tile[32][33];
    int b = blockIdx.z, c0 = blockIdx.y * 32, n0 = blockIdx.x * 32;
    int tx = threadIdx.x & 31, ty = threadIdx.x >> 5;
    const float* xb = x + ((size_t)b * CH + c0) * NPIX;
    #pragma unroll
    for (int k = 0; k < 4; k++) {
        int c = ty + k * 8;
        float sc = g_scale[b * CH + c0 + c], sh = g_shift[b * CH + c0 + c];
        tile[c][tx] = fmaf(xb[(size_t)c * NPIX + n0 + tx], sc, sh);
    }
    __syncthreads();
    bf16* dst = g_hT + (size_t)b * NPIX * CH;
    #pragma unroll
    for (int k = 0; k < 4; k++) {
        int n = ty + k * 8;
        dst[(size_t)(n0 + n) * CH + c0 + tx] = __float2bfloat16(tile[tx][n]);
    }
}

// ========== QK: D[n][o] = hT[n,:]·Wqk[o,:],  o<256 -> qT, else -> kT ==========
__global__ __launch_bounds__(128, 2) void qk_gemm() {
    const int b = blockIdx.z, m0 = blockIdx.y * 128, n0 = blockIdx.x * 128;
    float acc[4][8][4] = {};
    gemm_core<CH / BKC>(g_hT + (size_t)b * NPIX * CH + (size_t)m0 * CH, CH,
                        g_wqk + (size_t)n0 * CH, CH, acc);
    const int wid = threadIdx.x >> 5, lane = threadIdx.x & 31, gr = lane >> 2, tg = lane & 3;
    const int wm = wid >> 1, wn = wid & 1;
    bf16* dst = (n0 < 256 ? g_qT : g_kT) + (size_t)b * NPIX * CH;
    const int c0 = n0 & 255;
    #pragma unroll
    for (int i = 0; i < 4; i++) {
        int row = m0 + wm * 64 + i * 16 + gr;
        #pragma unroll
        for (int j = 0; j < 8; j++) {
            int col = c0 + wn * 64 + j * 8 + tg * 2;
            *(uint32_t*)&dst[(size_t)row * CH + col]       = pk2(acc[i][j][0], acc[i][j][1]);
            *(uint32_t*)&dst[(size_t)(row + 8) * CH + col] = pk2(acc[i][j][2], acc[i][j][3]);
        }
    }
}

// ========== V: D[c][m] = Wv[c,:]·hT[m,:] -> g_v[c][m] ==========
__global__ __launch_bounds__(128, 2) void v_gemm() {
    const int b = blockIdx.z, m0 = blockIdx.y * 128, n0 = blockIdx.x * 128;
    float acc[4][8][4] = {};
    gemm_core<CH / BKC>(g_wv + (size_t)m0 * CH, CH,
                        g_hT + (size_t)b * NPIX * CH + (size_t)n0 * CH, CH, acc);
    const int wid = threadIdx.x >> 5, lane = threadIdx.x & 31, gr = lane >> 2, tg = lane & 3;
    const int wm = wid >> 1, wn = wid & 1;
    bf16* dst = g_v + (size_t)b * CH * NPIX;
    #pragma unroll
    for (int i = 0; i < 4; i++) {
        int row = m0 + wm * 64 + i * 16 + gr;
        #pragma unroll
        for (int j = 0; j < 8; j++) {
            int col = n0 + wn * 64 + j * 8 + tg * 2;
            *(uint32_t*)&dst[(size_t)row * NPIX + col]       = pk2(acc[i][j][0], acc[i][j][1]);
            *(uint32_t*)&dst[(size_t)(row + 8) * NPIX + col] = pk2(acc[i][j][2], acc[i][j][3]);
        }
    }
}

// ========== S[n][m] = qT[n,:]·kT[m,:]  (fp32 out) ==========
__global__ __launch_bounds__(128, 2) void s_gemm() {
    const int b = blockIdx.z, m0 = blockIdx.y * 128, n0 = blockIdx.x * 128;
    float acc[4][8][4] = {};
    gemm_core<CH / BKC>(g_qT + (size_t)b * NPIX * CH + (size_t)m0 * CH, CH,
                        g_kT + (size_t)b * NPIX * CH + (size_t)n0 * CH, CH, acc);
    const int wid = threadIdx.x >> 5, lane = threadIdx.x & 31, gr = lane >> 2, tg = lane & 3;
    const int wm = wid >> 1, wn = wid & 1;
    float* dst = g_S + (size_t)b * NPIX * NPIX;
    #pragma unroll
    for (int i = 0; i < 4; i++) {
        int row = m0 + wm * 64 + i * 16 + gr;
        #pragma unroll
        for (int j = 0; j < 8; j++) {
            int col = n0 + wn * 64 + j * 8 + tg * 2;
            *(float2*)&dst[(size_t)row * NPIX + col]       = make_float2(acc[i][j][0], acc[i][j][1]);
            *(float2*)&dst[(size_t)(row + 8) * NPIX + col] = make_float2(acc[i][j][2], acc[i][j][3]);
        }
    }
}

// ================= row softmax: S fp32 -> P bf16 =================
__global__ __launch_bounds__(256) void softmax_rows() {
    const float4* p = (const float4*)(g_S + (size_t)blockIdx.x * NPIX);
    bf16* q = g_P + (size_t)blockIdx.x * NPIX;
    const int t = threadIdx.x;
    float4 v = p[t];
    float mx = fmaxf(fmaxf(v.x, v.y), fmaxf(v.z, v.w));
    #pragma unroll
    for (int o = 16; o; o >>= 1) mx = fmaxf(mx, __shfl_xor_sync(~0u, mx, o));
    __shared__ float red[8];
    if ((t & 31) == 0) red[t >> 5] = mx;
    __syncthreads();
    mx = red[0];
    #pragma unroll
    for (int i = 1; i < 8; i++) mx = fmaxf(mx, red[i]);
    __syncthreads();
    v.x = __expf(v.x - mx); v.y = __expf(v.y - mx);
    v.z = __expf(v.z - mx); v.w = __expf(v.w - mx);
    float s = v.x + v.y + v.z + v.w;
    #pragma unroll
    for (int o = 16; o; o >>= 1) s += __shfl_xor_sync(~0u, s, o);
    if ((t & 31) == 0) red[t >> 5] = s;
    __syncthreads();
    s = 0.f;
    #pragma unroll
    for (int i = 0; i < 8; i++) s += red[i];
    float inv = 1.f / s;
    uint2 out;
    out.x = pk2(v.x * inv, v.y * inv);
    out.y = pk2(v.z * inv, v.w * inv);
    *(uint2*)&q[t * 4] = out;
}

// ========== O[n][c] = P[n,:]·v[c,:] -> g_out bf16 ==========
__global__ __launch_bounds__(128, 2) void o_gemm() {
    const int b = blockIdx.z, m0 = blockIdx.y * 128, n0 = blockIdx.x * 128;
    float acc[4][8][4] = {};
    gemm_core<NPIX / BKC>(g_P + (size_t)b * NPIX * NPIX + (size_t)m0 * NPIX, NPIX,
                          g_v + (size_t)b * CH * NPIX + (size_t)n0 * NPIX, NPIX, acc);
    const int wid = threadIdx.x >> 5, lane = threadIdx.x & 31, gr = lane >> 2, tg = lane & 3;
    const int wm = wid >> 1, wn = wid & 1;
    bf16* dst = g_out + (size_t)b * NPIX * CH;
    #pragma unroll
    for (int i = 0; i < 4; i++) {
        int row = m0 + wm * 64 + i * 16 + gr;
        #pragma unroll
        for (int j = 0; j < 8; j++) {
            int col = n0 + wn * 64 + j * 8 + tg * 2;
            *(uint32_t*)&dst[(size_t)row * CH + col]       = pk2(acc[i][j][0], acc[i][j][1]);
            *(uint32_t*)&dst[(size_t)(row + 8) * CH + col] = pk2(acc[i][j][2], acc[i][j][3]);
        }
    }
}

// ========== proj: y[o][n] = x + pb[o] + Wp[o,:]·out[n,:] ==========
__global__ __launch_bounds__(128, 2) void proj_gemm(const float* __restrict__ x,
                                                    const float* __restrict__ pb,
                                                    float* __restrict__ y) {
    const int b = blockIdx.z, m0 = blockIdx.y * 128, n0 = blockIdx.x * 128;
    float acc[4][8][4] = {};
    gemm_core<CH / BKC>(g_wp + (size_t)m0 * CH, CH,
                        g_out + (size_t)b * NPIX * CH + (size_t)n0 * CH, CH, acc);
    const int wid = threadIdx.x >> 5, lane = threadIdx.x & 31, gr = lane >> 2, tg = lane & 3;
    const int wm = wid >> 1, wn = wid & 1;
    const float* xb = x + (size_t)b * CH * NPIX;
    float* yb = y + (size_t)b * CH * NPIX;
    #pragma unroll
    for (int i = 0; i < 4; i++) {
        int row = m0 + wm * 64 + i * 16 + gr;
        float b0 = pb[row], b1 = pb[row + 8];
        #pragma unroll
        for (int j = 0; j < 8; j++) {
            int col = n0 + wn * 64 + j * 8 + tg * 2;
            size_t i0 = (size_t)row * NPIX + col;
            size_t i1 = (size_t)(row + 8) * NPIX + col;
            float2 x0 = *(const float2*)&xb[i0];
            float2 x1 = *(const float2*)&xb[i1];
            *(float2*)&yb[i0] = make_float2(x0.x + b0 + acc[i][j][0], x0.y + b0 + acc[i][j][1]);
            *(float2*)&yb[i1] = make_float2(x1.x + b1 + acc[i][j][2], x1.y + b1 + acc[i][j][3]);
        }
    }
}

extern "C" void kernel_launch(void* const* d_in, const int* in_sizes, int n_in,
                              void* d_out, int out_size) {
    const float* x      = (const float*)d_in[0];
    const float* norm_w = (const float*)d_in[1];
    const float* norm_b = (const float*)d_in[2];
    const float* qkv_w  = (const float*)d_in[3];
    const float* proj_w = (const float*)d_in[4];
    const float* proj_b = (const float*)d_in[5];
    float* y = (float*)d_out;

    cudaFuncSetAttribute(qk_gemm,   cudaFuncAttributeMaxDynamicSharedMemorySize, SMEM_REQ);
    cudaFuncSetAttribute(v_gemm,    cudaFuncAttributeMaxDynamicSharedMemorySize, SMEM_REQ);
    cudaFuncSetAttribute(s_gemm,    cudaFuncAttributeMaxDynamicSharedMemorySize, SMEM_REQ);
    cudaFuncSetAttribute(o_gemm,    cudaFuncAttributeMaxDynamicSharedMemorySize, SMEM_REQ);
    cudaFuncSetAttribute(proj_gemm, cudaFuncAttributeMaxDynamicSharedMemorySize, SMEM_REQ);

    gn_stats<<<BATCH * GROUPS, 256>>>(x, norm_w, norm_b);
    wcvt<<<(1024 * CH) / (256 * 4), 256>>>(qkv_w, proj_w);
    ht_kernel<<<dim3(NPIX / 32, CH / 32, BATCH), 256>>>(x);
    qk_gemm<<<dim3(4, NPIX / 128, BATCH), 128, SMEM_REQ>>>();
    v_gemm<<<dim3(NPIX / 128, 2, BATCH), 128, SMEM_REQ>>>();
    s_gemm<<<dim3(NPIX / 128, NPIX / 128, BATCH), 128, SMEM_REQ>>>();
    softmax_rows<<<BATCH * NPIX, 256>>>();
    o_gemm<<<dim3(2, NPIX / 128, BATCH), 128, SMEM_REQ>>>();
    proj_gemm<<<dim3(NPIX / 128, 2, BATCH), 128, SMEM_REQ>>>(x, proj_b, y);
}

// round 8
// speedup vs baseline: 7.6965x; 1.1939x over previous
#include <cuda_runtime.h>
#include <cuda_bf16.h>
#include <stdint.h>

#define BATCH 32
#define CH    256
#define NPIX  1024
#define GROUPS 8
#define CPG   32
#define EPSV  1e-5f

#define BKC 64
#define TILE_B  16384
#define STAGE_B (2 * TILE_B)
#define NSG 3
#define SMEM_REQ (NSG * STAGE_B)     // 98304 for gemm kernels
#define FA_SMEM 196608               // 192KB: Q 64K + K 64K + V 64K

typedef __nv_bfloat16 bf16;

// ---- scratch ----
__device__ bf16 g_hT [(size_t)BATCH * NPIX * CH];
__device__ bf16 g_qT [(size_t)BATCH * NPIX * CH];    // [b][n][c] (W_q pre-scaled 1/16)
__device__ bf16 g_kT [(size_t)BATCH * NPIX * CH];    // [b][m][c]
__device__ bf16 g_v  [(size_t)BATCH * CH * NPIX];    // [b][c][m]
__device__ bf16 g_out[(size_t)BATCH * NPIX * CH];    // [b][n][c]
__device__ bf16 g_wqk[(size_t)512 * CH];
__device__ bf16 g_wv [(size_t)CH * CH];
__device__ bf16 g_wp [(size_t)CH * CH];
__device__ float g_scale[BATCH * CH];
__device__ float g_shift[BATCH * CH];

// ================= helpers =================
__device__ __forceinline__ uint32_t smem_u32(const void* p) {
    uint32_t a;
    asm("{ .reg .u64 t; cvta.to.shared.u64 t, %1; cvt.u32.u64 %0, t; }" : "=r"(a) : "l"(p));
    return a;
}
__device__ __forceinline__ void cpa16(uint32_t d, const void* s) {
    asm volatile("cp.async.cg.shared.global [%0], [%1], 16;" :: "r"(d), "l"(s));
}
__device__ __forceinline__ uint32_t pk2(float lo, float hi) {
    uint32_t r;
    asm("cvt.rn.bf16x2.f32 %0, %1, %2;" : "=r"(r) : "f"(hi), "f"(lo));
    return r;
}
__device__ __forceinline__ void mma_bf16(float c[4], const uint32_t a[4], uint32_t b0, uint32_t b1) {
    asm volatile("mma.sync.aligned.m16n8k16.row.col.f32.bf16.bf16.f32 "
                 "{%0,%1,%2,%3}, {%4,%5,%6,%7}, {%8,%9}, {%0,%1,%2,%3};\n"
                 : "+f"(c[0]), "+f"(c[1]), "+f"(c[2]), "+f"(c[3])
                 : "r"(a[0]), "r"(a[1]), "r"(a[2]), "r"(a[3]), "r"(b0), "r"(b1));
}
__device__ __forceinline__ void ldmx4(uint32_t r[4], uint32_t addr) {
    asm volatile("ldmatrix.sync.aligned.m8n8.x4.shared.b16 {%0,%1,%2,%3}, [%4];"
                 : "=r"(r[0]), "=r"(r[1]), "=r"(r[2]), "=r"(r[3]) : "r"(addr));
}
// 128B-row swizzle: row r, 16B chunk kc in [0,8)
__device__ __forceinline__ uint32_t swz(uint32_t r, uint32_t kc) {
    return r * 128 + ((kc ^ (r & 7)) << 4);
}

// ====== bf16 mma.sync GEMM core (unchanged from R7) ======
template <int NT>
__device__ __forceinline__ void gemm_core(const bf16* __restrict__ A, int lda,
                                          const bf16* __restrict__ B, int ldb,
                                          float (&acc)[4][8][4]) {
    extern __shared__ char sh[];
    const uint32_t sbase = smem_u32(sh);
    const int tid = threadIdx.x, lane = tid & 31, wid = tid >> 5;
    const int wm = wid >> 1, wn = wid & 1;
    const int dl  = (lane & 7) + ((lane >> 3) & 1) * 8;
    const int dkc = lane >> 4;

    auto load_stage = [&](int s, int t) {
        uint32_t ab = sbase + s * STAGE_B;
        uint32_t bb = ab + TILE_B;
        const bf16* ga = A + t * BKC;
        const bf16* gb = B + t * BKC;
        #pragma unroll
        for (int it = 0; it < 8; it++) {
            int c = tid + it * 128;
            int r = c >> 3, kc = c & 7;
            uint32_t o = swz(r, kc);
            cpa16(ab + o, ga + (size_t)r * lda + kc * 8);
            cpa16(bb + o, gb + (size_t)r * ldb + kc * 8);
        }
        asm volatile("cp.async.commit_group;");
    };

    load_stage(0, 0);
    if (NT > 1) load_stage(1, 1);

    #pragma unroll 1
    for (int t = 0; t < NT; t++) {
        if (t + 1 < NT) asm volatile("cp.async.wait_group 1;");
        else            asm volatile("cp.async.wait_group 0;");
        __syncthreads();
        if (t + 2 < NT) load_stage((t + 2) % NSG, t + 2);

        uint32_t ab = sbase + (t % NSG) * STAGE_B;
        uint32_t bb = ab + TILE_B;
        #pragma unroll
        for (int ks = 0; ks < 4; ks++) {
            uint32_t a[4][4], b2[4][4];
            #pragma unroll
            for (int i = 0; i < 4; i++)
                ldmx4(a[i], ab + swz(wm * 64 + i * 16 + dl, ks * 2 + dkc));
            #pragma unroll
            for (int jj = 0; jj < 4; jj++)
                ldmx4(b2[jj], bb + swz(wn * 64 + jj * 16 + dl, ks * 2 + dkc));
            #pragma unroll
            for (int i = 0; i < 4; i++)
                #pragma unroll
                for (int j = 0; j < 8; j++)
                    mma_bf16(acc[i][j], a[i], b2[j >> 1][j & 1], b2[j >> 1][(j & 1) + 2]);
        }
    }
}

// ================= GroupNorm stats =================
__global__ __launch_bounds__(256) void gn_stats(const float* __restrict__ x,
                                                const float* __restrict__ nw,
                                                const float* __restrict__ nb) {
    int bg = blockIdx.x;
    int b = bg / GROUPS, g = bg % GROUPS;
    const float4* p4 = (const float4*)(x + ((size_t)b * CH + (size_t)g * CPG) * NPIX);
    float s = 0.f, sq = 0.f;
    for (int i = threadIdx.x; i < CPG * NPIX / 4; i += 256) {
        float4 v = p4[i];
        s += v.x + v.y + v.z + v.w;
        sq += v.x * v.x + v.y * v.y + v.z * v.z + v.w * v.w;
    }
    #pragma unroll
    for (int o = 16; o; o >>= 1) {
        s  += __shfl_xor_sync(~0u, s, o);
        sq += __shfl_xor_sync(~0u, sq, o);
    }
    __shared__ float ss[8], ssq[8];
    if ((threadIdx.x & 31) == 0) { ss[threadIdx.x >> 5] = s; ssq[threadIdx.x >> 5] = sq; }
    __syncthreads();
    if (threadIdx.x < CPG) {
        float st = 0.f, sqt = 0.f;
        #pragma unroll
        for (int i = 0; i < 8; i++) { st += ss[i]; sqt += ssq[i]; }
        const float inv_n = 1.f / (float)(CPG * NPIX);
        float mean = st * inv_n;
        float var  = sqt * inv_n - mean * mean;
        float rstd = rsqrtf(var + EPSV);
        int c = g * CPG + threadIdx.x;
        float sc = rstd * nw[c];
        g_scale[b * CH + c] = sc;
        g_shift[b * CH + c] = nb[c] - mean * sc;
    }
}

// ================= weights -> bf16 =================
__global__ __launch_bounds__(256) void wcvt(const float* __restrict__ qkv_w,
                                            const float* __restrict__ proj_w) {
    int idx = blockIdx.x * 256 + threadIdx.x;
    #pragma unroll
    for (int u = 0; u < 4; u++) {
        int e = idx * 4 + u;
        if (e < 768 * CH) {
            int row = e / CH;
            float v = qkv_w[e];
            if (row < CH) v *= 0.0625f;
            if (row < 512) g_wqk[e] = __float2bfloat16(v);
            else           g_wv[e - 512 * CH] = __float2bfloat16(v);
        } else {
            int e2 = e - 768 * CH;
            g_wp[e2] = __float2bfloat16(proj_w[e2]);
        }
    }
}

// ================= normalize + transpose =================
__global__ __launch_bounds__(256) void ht_kernel(const float* __restrict__ x) {
    __shared__ float tile[32][33];
    int b = blockIdx.z, c0 = blockIdx.y * 32, n0 = blockIdx.x * 32;
    int tx = threadIdx.x & 31, ty = threadIdx.x >> 5;
    const float* xb = x + ((size_t)b * CH + c0) * NPIX;
    #pragma unroll
    for (int k = 0; k < 4; k++) {
        int c = ty + k * 8;
        float sc = g_scale[b * CH + c0 + c], sh = g_shift[b * CH + c0 + c];
        tile[c][tx] = fmaf(xb[(size_t)c * NPIX + n0 + tx], sc, sh);
    }
    __syncthreads();
    bf16* dst = g_hT + (size_t)b * NPIX * CH;
    #pragma unroll
    for (int k = 0; k < 4; k++) {
        int n = ty + k * 8;
        dst[(size_t)(n0 + n) * CH + c0 + tx] = __float2bfloat16(tile[tx][n]);
    }
}

// ========== QK GEMM ==========
__global__ __launch_bounds__(128, 2) void qk_gemm() {
    const int b = blockIdx.z, m0 = blockIdx.y * 128, n0 = blockIdx.x * 128;
    float acc[4][8][4] = {};
    gemm_core<CH / BKC>(g_hT + (size_t)b * NPIX * CH + (size_t)m0 * CH, CH,
                        g_wqk + (size_t)n0 * CH, CH, acc);
    const int wid = threadIdx.x >> 5, lane = threadIdx.x & 31, gr = lane >> 2, tg = lane & 3;
    const int wm = wid >> 1, wn = wid & 1;
    bf16* dst = (n0 < 256 ? g_qT : g_kT) + (size_t)b * NPIX * CH;
    const int c0 = n0 & 255;
    #pragma unroll
    for (int i = 0; i < 4; i++) {
        int row = m0 + wm * 64 + i * 16 + gr;
        #pragma unroll
        for (int j = 0; j < 8; j++) {
            int col = c0 + wn * 64 + j * 8 + tg * 2;
            *(uint32_t*)&dst[(size_t)row * CH + col]       = pk2(acc[i][j][0], acc[i][j][1]);
            *(uint32_t*)&dst[(size_t)(row + 8) * CH + col] = pk2(acc[i][j][2], acc[i][j][3]);
        }
    }
}

// ========== V GEMM ==========
__global__ __launch_bounds__(128, 2) void v_gemm() {
    const int b = blockIdx.z, m0 = blockIdx.y * 128, n0 = blockIdx.x * 128;
    float acc[4][8][4] = {};
    gemm_core<CH / BKC>(g_wv + (size_t)m0 * CH, CH,
                        g_hT + (size_t)b * NPIX * CH + (size_t)n0 * CH, CH, acc);
    const int wid = threadIdx.x >> 5, lane = threadIdx.x & 31, gr = lane >> 2, tg = lane & 3;
    const int wm = wid >> 1, wn = wid & 1;
    bf16* dst = g_v + (size_t)b * CH * NPIX;
    #pragma unroll
    for (int i = 0; i < 4; i++) {
        int row = m0 + wm * 64 + i * 16 + gr;
        #pragma unroll
        for (int j = 0; j < 8; j++) {
            int col = n0 + wn * 64 + j * 8 + tg * 2;
            *(uint32_t*)&dst[(size_t)row * NPIX + col]       = pk2(acc[i][j][0], acc[i][j][1]);
            *(uint32_t*)&dst[(size_t)(row + 8) * NPIX + col] = pk2(acc[i][j][2], acc[i][j][3]);
        }
    }
}

// ========== fused flash attention: g_out[n][c] = softmax(q·kT)·v ==========
// grid (8, BATCH), 256 threads. Each warp: 16 query rows. SMEM: Q 64K | K 64K | V 64K.
__global__ __launch_bounds__(256, 1) void flash_attn() {
    extern __shared__ char sh[];
    const uint32_t sq = smem_u32(sh);
    const uint32_t sk = sq + 65536;
    const uint32_t sv = sq + 131072;
    const int b = blockIdx.y, nblk = blockIdx.x * 128;
    const int tid = threadIdx.x, lane = tid & 31, wid = tid >> 5;
    const int q0 = wid * 16;
    const int gr = lane >> 2, tg = lane & 3;
    const int dl = lane & 15, dkc = lane >> 4;

    const bf16* Qg = g_qT + (size_t)b * NPIX * CH + (size_t)nblk * CH;
    const bf16* Kg = g_kT + (size_t)b * NPIX * CH;
    const bf16* Vg = g_v  + (size_t)b * CH * NPIX;

    auto load_qk = [&](uint32_t dstbase, const bf16* src, int rowoff) {
        #pragma unroll
        for (int it = 0; it < 16; it++) {
            int c = tid + it * 256;
            int p = c >> 10, rr = (c >> 3) & 127, kc = c & 7;
            cpa16(dstbase + p * 16384 + swz(rr, kc),
                  src + (size_t)(rowoff + rr) * CH + p * 64 + kc * 8);
        }
        asm volatile("cp.async.commit_group;");
    };
    auto load_v = [&](int j) {
        #pragma unroll
        for (int it = 0; it < 16; it++) {
            int c = tid + it * 256;
            int p = c >> 11, rr = (c >> 3) & 255, kc = c & 7;
            cpa16(sv + p * 32768 + swz(rr, kc),
                  Vg + (size_t)rr * NPIX + j * 128 + p * 64 + kc * 8);
        }
        asm volatile("cp.async.commit_group;");
    };

    // prologue: Q+K0 (group), V0 (group)
    {
        #pragma unroll
        for (int it = 0; it < 16; it++) {
            int c = tid + it * 256;
            int p = c >> 10, rr = (c >> 3) & 127, kc = c & 7;
            cpa16(sq + p * 16384 + swz(rr, kc), Qg + (size_t)rr * CH + p * 64 + kc * 8);
            cpa16(sk + p * 16384 + swz(rr, kc), Kg + (size_t)rr * CH + p * 64 + kc * 8);
        }
        asm volatile("cp.async.commit_group;");
    }
    load_v(0);
    asm volatile("cp.async.wait_group 1;");
    __syncthreads();

    float oacc[32][4] = {};
    float m0 = -1e30f, m1 = -1e30f, l0 = 0.f, l1 = 0.f;

    #pragma unroll 1
    for (int j = 0; j < 8; j++) {
        // ---- S = Q · K_j^T  (warp: 16 q x 128 m) ----
        float sacc[16][4];
        #pragma unroll
        for (int t = 0; t < 16; t++)
            sacc[t][0] = sacc[t][1] = sacc[t][2] = sacc[t][3] = 0.f;
        #pragma unroll
        for (int ks = 0; ks < 16; ks++) {
            uint32_t a[4];
            ldmx4(a, sq + (ks >> 2) * 16384 + swz(q0 + dl, ((ks & 3) << 1) + dkc));
            #pragma unroll
            for (int jj = 0; jj < 8; jj++) {
                uint32_t bb[4];
                ldmx4(bb, sk + (ks >> 2) * 16384 + swz(jj * 16 + dl, ((ks & 3) << 1) + dkc));
                mma_bf16(sacc[2 * jj],     a, bb[0], bb[2]);
                mma_bf16(sacc[2 * jj + 1], a, bb[1], bb[3]);
            }
        }
        // ---- online softmax update (registers) ----
        float rx0 = -1e30f, rx1 = -1e30f;
        #pragma unroll
        for (int t = 0; t < 16; t++) {
            rx0 = fmaxf(rx0, fmaxf(sacc[t][0], sacc[t][1]));
            rx1 = fmaxf(rx1, fmaxf(sacc[t][2], sacc[t][3]));
        }
        rx0 = fmaxf(rx0, __shfl_xor_sync(~0u, rx0, 1)); rx0 = fmaxf(rx0, __shfl_xor_sync(~0u, rx0, 2));
        rx1 = fmaxf(rx1, __shfl_xor_sync(~0u, rx1, 1)); rx1 = fmaxf(rx1, __shfl_xor_sync(~0u, rx1, 2));
        float mn0 = fmaxf(m0, rx0), mn1 = fmaxf(m1, rx1);
        float al0 = __expf(m0 - mn0), al1 = __expf(m1 - mn1);
        m0 = mn0; m1 = mn1;
        float rs0 = 0.f, rs1 = 0.f;
        #pragma unroll
        for (int t = 0; t < 16; t++) {
            sacc[t][0] = __expf(sacc[t][0] - mn0); rs0 += sacc[t][0];
            sacc[t][1] = __expf(sacc[t][1] - mn0); rs0 += sacc[t][1];
            sacc[t][2] = __expf(sacc[t][2] - mn1); rs1 += sacc[t][2];
            sacc[t][3] = __expf(sacc[t][3] - mn1); rs1 += sacc[t][3];
        }
        l0 = l0 * al0 + rs0;   // per-thread partial; reduced across tg at end
        l1 = l1 * al1 + rs1;
        #pragma unroll
        for (int t = 0; t < 32; t++) {
            oacc[t][0] *= al0; oacc[t][1] *= al0;
            oacc[t][2] *= al1; oacc[t][3] *= al1;
        }

        __syncthreads();                       // all warps done reading K_j
        if (j < 7) load_qk(sk, Kg, (j + 1) * 128);
        if (j < 7) asm volatile("cp.async.wait_group 1;");   // V_j ready
        else       asm volatile("cp.async.wait_group 0;");
        __syncthreads();

        // ---- O += P · V_j  (warp: 16 q x 256 c, K-dim = 128 m) ----
        #pragma unroll
        for (int kp = 0; kp < 8; kp++) {
            uint32_t a[4];
            a[0] = pk2(sacc[2 * kp][0],     sacc[2 * kp][1]);
            a[1] = pk2(sacc[2 * kp][2],     sacc[2 * kp][3]);
            a[2] = pk2(sacc[2 * kp + 1][0], sacc[2 * kp + 1][1]);
            a[3] = pk2(sacc[2 * kp + 1][2], sacc[2 * kp + 1][3]);
            #pragma unroll
            for (int cc = 0; cc < 16; cc++) {
                uint32_t bb[4];
                ldmx4(bb, sv + (kp >> 2) * 32768 + swz(cc * 16 + dl, ((kp & 3) << 1) + dkc));
                mma_bf16(oacc[2 * cc],     a, bb[0], bb[2]);
                mma_bf16(oacc[2 * cc + 1], a, bb[1], bb[3]);
            }
        }
        __syncthreads();                       // all warps done reading V_j
        if (j < 7) {
            load_v(j + 1);
            asm volatile("cp.async.wait_group 1;");          // K_{j+1} ready
            __syncthreads();
        }
    }

    // ---- epilogue: reduce l across tg, normalize, store bf16 ----
    l0 += __shfl_xor_sync(~0u, l0, 1); l0 += __shfl_xor_sync(~0u, l0, 2);
    l1 += __shfl_xor_sync(~0u, l1, 1); l1 += __shfl_xor_sync(~0u, l1, 2);
    float inv0 = 1.f / l0, inv1 = 1.f / l1;
    bf16* dst = g_out + (size_t)b * NPIX * CH;
    int row0 = nblk + q0 + gr, row1 = row0 + 8;
    #pragma unroll
    for (int t = 0; t < 32; t++) {
        int col = t * 8 + tg * 2;
        *(uint32_t*)&dst[(size_t)row0 * CH + col] = pk2(oacc[t][0] * inv0, oacc[t][1] * inv0);
        *(uint32_t*)&dst[(size_t)row1 * CH + col] = pk2(oacc[t][2] * inv1, oacc[t][3] * inv1);
    }
}

// ========== proj: y[o][n] = x + pb[o] + Wp[o,:]·out[n,:] ==========
__global__ __launch_bounds__(128, 2) void proj_gemm(const float* __restrict__ x,
                                                    const float* __restrict__ pb,
                                                    float* __restrict__ y) {
    const int b = blockIdx.z, m0 = blockIdx.y * 128, n0 = blockIdx.x * 128;
    float acc[4][8][4] = {};
    gemm_core<CH / BKC>(g_wp + (size_t)m0 * CH, CH,
                        g_out + (size_t)b * NPIX * CH + (size_t)n0 * CH, CH, acc);
    const int wid = threadIdx.x >> 5, lane = threadIdx.x & 31, gr = lane >> 2, tg = lane & 3;
    const int wm = wid >> 1, wn = wid & 1;
    const float* xb = x + (size_t)b * CH * NPIX;
    float* yb = y + (size_t)b * CH * NPIX;
    #pragma unroll
    for (int i = 0; i < 4; i++) {
        int row = m0 + wm * 64 + i * 16 + gr;
        float b0 = pb[row], b1 = pb[row + 8];
        #pragma unroll
        for (int j = 0; j < 8; j++) {
            int col = n0 + wn * 64 + j * 8 + tg * 2;
            size_t i0 = (size_t)row * NPIX + col;
            size_t i1 = (size_t)(row + 8) * NPIX + col;
            float2 x0 = *(const float2*)&xb[i0];
            float2 x1 = *(const float2*)&xb[i1];
            *(float2*)&yb[i0] = make_float2(x0.x + b0 + acc[i][j][0], x0.y + b0 + acc[i][j][1]);
            *(float2*)&yb[i1] = make_float2(x1.x + b1 + acc[i][j][2], x1.y + b1 + acc[i][j][3]);
        }
    }
}

extern "C" void kernel_launch(void* const* d_in, const int* in_sizes, int n_in,
                              void* d_out, int out_size) {
    const float* x      = (const float*)d_in[0];
    const float* norm_w = (const float*)d_in[1];
    const float* norm_b = (const float*)d_in[2];
    const float* qkv_w  = (const float*)d_in[3];
    const float* proj_w = (const float*)d_in[4];
    const float* proj_b = (const float*)d_in[5];
    float* y = (float*)d_out;

    cudaFuncSetAttribute(qk_gemm,   cudaFuncAttributeMaxDynamicSharedMemorySize, SMEM_REQ);
    cudaFuncSetAttribute(v_gemm,    cudaFuncAttributeMaxDynamicSharedMemorySize, SMEM_REQ);
    cudaFuncSetAttribute(proj_gemm, cudaFuncAttributeMaxDynamicSharedMemorySize, SMEM_REQ);
    cudaFuncSetAttribute(flash_attn, cudaFuncAttributeMaxDynamicSharedMemorySize, FA_SMEM);

    gn_stats<<<BATCH * GROUPS, 256>>>(x, norm_w, norm_b);
    wcvt<<<(1024 * CH) / (256 * 4), 256>>>(qkv_w, proj_w);
    ht_kernel<<<dim3(NPIX / 32, CH / 32, BATCH), 256>>>(x);
    qk_gemm<<<dim3(4, NPIX / 128, BATCH), 128, SMEM_REQ>>>();
    v_gemm<<<dim3(NPIX / 128, 2, BATCH), 128, SMEM_REQ>>>();
    flash_attn<<<dim3(NPIX / 128, BATCH), 256, FA_SMEM>>>();
    proj_gemm<<<dim3(NPIX / 128, 2, BATCH), 128, SMEM_REQ>>>(x, proj_b, y);
}